// round 12
// baseline (speedup 1.0000x reference)
#include <cuda_runtime.h>
#include <cuda_bf16.h>
#include <cstdint>
#include <cstddef>

#define BATCH 32
#define NPTS1 8192
#define M1 512
#define KNN1 32
#define M2 128
#define KNN2 64
#define NPTS2 512

// ---------------- scratch (static device globals) ----------------
__device__ float g_xyz[BATCH * NPTS1 * 3];
__device__ float g_newxyz1[BATCH * M1 * 3];
__device__ float g_newxyz2[BATCH * M2 * 3];
__device__ int   g_ball1[BATCH * M1 * KNN1];
__device__ int   g_ball2[BATCH * M2 * KNN2];

// split bf16 planes
__device__ uint16_t g_whi[801792];
__device__ uint16_t g_wlo[801792];
__device__ uint16_t g_grpHi[262144 * 144];
__device__ uint16_t g_grpLo[262144 * 144];
__device__ uint16_t g_aHi[524288 * 64];
__device__ uint16_t g_aLo[524288 * 64];
__device__ uint16_t g_bHi[524288 * 64];
__device__ uint16_t g_bLo[524288 * 64];
__device__ uint16_t g_f1Hi[16384 * 128];
__device__ uint16_t g_f1Lo[16384 * 128];
__device__ uint16_t g_f2Hi[4096 * 256];
__device__ uint16_t g_f2Lo[4096 * 256];

__device__ float g_pool[BATCH * 1024];
__device__ float g_g1[BATCH * 512];
__device__ float g_g2[BATCH * 256];

// weight plane offsets (elements), K padded to multiple of 16
#define OW0 0        // 64 x 16   (K=3 padded)
#define OW1 1024     // 64 x 64
#define OW2 5120     // 128 x 64
#define OS0 13312    // 128 x 144 (K=131 padded)
#define OS1 31744    // 128 x 128
#define OS2 48128    // 256 x 128
#define OL0 80896    // 256 x 256
#define OL1 146432   // 512 x 256
#define OL2 277504   // 1024 x 512

// ---------------- helpers ----------------
__device__ __forceinline__ uint32_t smem_u32(const void* p) {
    uint32_t a;
    asm("{ .reg .u64 t; cvta.to.shared.u64 t, %1; cvt.u32.u64 %0, t; }" : "=r"(a) : "l"(p));
    return a;
}
__device__ __forceinline__ void ldmx4(uint32_t* r, uint32_t a) {
    asm volatile("ldmatrix.sync.aligned.m8n8.x4.shared.b16 {%0,%1,%2,%3}, [%4];"
                 : "=r"(r[0]), "=r"(r[1]), "=r"(r[2]), "=r"(r[3]) : "r"(a));
}
__device__ __forceinline__ void mma16816(float* c, const uint32_t* a, const uint32_t* b) {
    asm volatile("mma.sync.aligned.m16n8k16.row.col.f32.bf16.bf16.f32 "
                 "{%0,%1,%2,%3}, {%4,%5,%6,%7}, {%8,%9}, {%0,%1,%2,%3};"
                 : "+f"(c[0]), "+f"(c[1]), "+f"(c[2]), "+f"(c[3])
                 : "r"(a[0]), "r"(a[1]), "r"(a[2]), "r"(a[3]), "r"(b[0]), "r"(b[1]));
}
__device__ __forceinline__ uint32_t pack_bf(__nv_bfloat16 a, __nv_bfloat16 b) {
    return ((uint32_t)__bfloat16_as_ushort(b) << 16) | __bfloat16_as_ushort(a);
}
__device__ __forceinline__ void split1(float v, uint16_t& h, uint16_t& l) {
    __nv_bfloat16 hb = __float2bfloat16(v);
    h = __bfloat16_as_ushort(hb);
    l = __bfloat16_as_ushort(__float2bfloat16(v - __bfloat162float(hb)));
}
__device__ __forceinline__ void split2pack(float v0, float v1, uint32_t& ph, uint32_t& pl) {
    __nv_bfloat16 h0 = __float2bfloat16(v0), h1 = __float2bfloat16(v1);
    __nv_bfloat16 l0 = __float2bfloat16(v0 - __bfloat162float(h0));
    __nv_bfloat16 l1 = __float2bfloat16(v1 - __bfloat162float(h1));
    ph = pack_bf(h0, h1);
    pl = pack_bf(l0, l1);
}

// ---------------- transpose ----------------
__global__ void k_transpose(const float* __restrict__ pts) {
    int idx = blockIdx.x * blockDim.x + threadIdx.x;
    if (idx >= BATCH * 3 * NPTS1) return;
    int b = idx / (3 * NPTS1);
    int r = idx % (3 * NPTS1);
    int c = r / NPTS1;
    int n = r % NPTS1;
    g_xyz[(b * NPTS1 + n) * 3 + c] = pts[idx];
}

// ---------------- weight split: src[N,Kin] fp32 -> hi/lo[N,Kpad] bf16 ----------------
__global__ void k_wsplit(const float* __restrict__ src, uint16_t* __restrict__ hi,
                         uint16_t* __restrict__ lo, int N, int Kin, int Kpad) {
    int i = blockIdx.x * blockDim.x + threadIdx.x;
    if (i >= N * Kpad) return;
    int r = i / Kpad, k = i % Kpad;
    float v = (k < Kin) ? src[r * Kin + k] : 0.f;
    split1(v, hi[i], lo[i]);
}

// ---------------- farthest point sampling ----------------
template <int P, int NP, int MSEL>
__global__ void k_fps(const float* __restrict__ xyz, float* __restrict__ new_xyz) {
    int b = blockIdx.x, tid = threadIdx.x, T = blockDim.x;
    float px[P], py[P], pz[P], pd[P];
#pragma unroll
    for (int j = 0; j < P; j++) {
        int i = j * T + tid;
        const float* p = &xyz[(b * NP + i) * 3];
        px[j] = p[0]; py[j] = p[1]; pz[j] = p[2];
        pd[j] = 1e10f;
    }
    __shared__ float s_cx, s_cy, s_cz;
    __shared__ float s_val[32];
    __shared__ int   s_idx[32];
    if (tid == 0) {
        const float* p = &xyz[(size_t)b * NP * 3];
        s_cx = p[0]; s_cy = p[1]; s_cz = p[2];
        float* o = &new_xyz[(size_t)b * MSEL * 3];
        o[0] = p[0]; o[1] = p[1]; o[2] = p[2];
    }
    __syncthreads();
    int nw = T >> 5;
    for (int it = 1; it < MSEL; it++) {
        float cx = s_cx, cy = s_cy, cz = s_cz;
        float bv = -1.0f; int bi = NP;
#pragma unroll
        for (int j = 0; j < P; j++) {
            int i = j * T + tid;
            float dx = px[j] - cx, dy = py[j] - cy, dz = pz[j] - cz;
            float d = fmaf(dz, dz, fmaf(dy, dy, dx * dx));
            d = fminf(pd[j], d);
            pd[j] = d;
            if (d > bv || (d == bv && i < bi)) { bv = d; bi = i; }
        }
#pragma unroll
        for (int off = 16; off > 0; off >>= 1) {
            float ov = __shfl_down_sync(0xffffffffu, bv, off);
            int   oi = __shfl_down_sync(0xffffffffu, bi, off);
            if (ov > bv || (ov == bv && oi < bi)) { bv = ov; bi = oi; }
        }
        int w = tid >> 5;
        if ((tid & 31) == 0) { s_val[w] = bv; s_idx[w] = bi; }
        __syncthreads();
        if (w == 0) {
            int lane = tid & 31;
            bv = (lane < nw) ? s_val[lane] : -2.0f;
            bi = (lane < nw) ? s_idx[lane] : NP;
#pragma unroll
            for (int off = 16; off > 0; off >>= 1) {
                float ov = __shfl_down_sync(0xffffffffu, bv, off);
                int   oi = __shfl_down_sync(0xffffffffu, bi, off);
                if (ov > bv || (ov == bv && oi < bi)) { bv = ov; bi = oi; }
            }
            if (lane == 0) {
                const float* p = &xyz[((size_t)b * NP + bi) * 3];
                s_cx = p[0]; s_cy = p[1]; s_cz = p[2];
                float* o = &new_xyz[((size_t)b * MSEL + it) * 3];
                o[0] = p[0]; o[1] = p[1]; o[2] = p[2];
            }
        }
        __syncthreads();
    }
}

// ---------------- ball query ----------------
template <int NP, int MSEL, int KQ>
__global__ void k_ballquery(const float* __restrict__ xyz, const float* __restrict__ cent,
                            float R2, int* __restrict__ out) {
    int gw = (blockIdx.x * blockDim.x + threadIdx.x) >> 5;
    int lane = threadIdx.x & 31;
    if (gw >= BATCH * MSEL) return;
    int b = gw / MSEL, m = gw % MSEL;
    const float* cp = &cent[((size_t)b * MSEL + m) * 3];
    float cx = cp[0], cy = cp[1], cz = cp[2];
    const float* xb = &xyz[(size_t)b * NP * 3];
    int* o = &out[((size_t)b * MSEL + m) * KQ];
    int cnt = 0, first = -1;
#pragma unroll 4
    for (int base = 0; base < NP; base += 32) {
        int i = base + lane;
        const float* p = &xb[i * 3];
        float dx = p[0] - cx, dy = p[1] - cy, dz = p[2] - cz;
        float d = fmaf(dz, dz, fmaf(dy, dy, dx * dx));
        bool valid = d < R2;
        unsigned mk = __ballot_sync(0xffffffffu, valid);
        if (first < 0 && mk) first = base + __ffs(mk) - 1;
        int pos = cnt + __popc(mk & ((1u << lane) - 1u));
        if (valid && pos < KQ) o[pos] = i;
        cnt += __popc(mk);
    }
    if (cnt > KQ) cnt = KQ;
    for (int p = cnt + lane; p < KQ; p += 32) o[p] = first;
}

// ---------------- grouping: SA1 -> grp planes [524288, 16] bf16 hi/lo ----------------
__global__ void k_group1s() {
    int r = blockIdx.x * blockDim.x + threadIdx.x;
    if (r >= BATCH * M1 * KNN1) return;
    int g = r / KNN1;
    int b = g / M1;
    int i = g_ball1[r];
    const float* p = &g_xyz[((size_t)b * NPTS1 + i) * 3];
    const float* c = &g_newxyz1[(size_t)g * 3];
    float d0 = p[0] - c[0], d1 = p[1] - c[1], d2 = p[2] - c[2];
    uint32_t ph0, pl0, ph1, pl1;
    split2pack(d0, d1, ph0, pl0);
    split2pack(d2, 0.f, ph1, pl1);
    uint4 qh = make_uint4(ph0, ph1, 0u, 0u);
    uint4 ql = make_uint4(pl0, pl1, 0u, 0u);
    uint4 z = make_uint4(0u, 0u, 0u, 0u);
    ((uint4*)g_grpHi)[(size_t)r * 2] = qh;
    ((uint4*)g_grpHi)[(size_t)r * 2 + 1] = z;
    ((uint4*)g_grpLo)[(size_t)r * 2] = ql;
    ((uint4*)g_grpLo)[(size_t)r * 2 + 1] = z;
}

// ---------------- grouping: SA2 -> grp planes [262144, 144] bf16 hi/lo ----------------
__global__ void k_group2s() {
    int gw = (blockIdx.x * blockDim.x + threadIdx.x) >> 5;
    int lane = threadIdx.x & 31;
    if (gw >= BATCH * M2 * KNN2) return;
    int g = gw / KNN2;
    int b = g / M2;
    int i = g_ball2[gw];
    uint16_t* oh = &g_grpHi[(size_t)gw * 144];
    uint16_t* ol = &g_grpLo[(size_t)gw * 144];
    const float* c = &g_newxyz2[(size_t)g * 3];
    const float* p = &g_newxyz1[((size_t)b * NPTS2 + i) * 3];
    if (lane < 3) {
        float d = p[lane] - c[lane];
        uint16_t h, l;
        split1(d, h, l);
        oh[lane] = h; ol[lane] = l;
    }
    if (lane >= 3 && lane < 16) {  // zero tail cols 131..143
        oh[128 + lane] = 0; ol[128 + lane] = 0;
    }
    const uint16_t* fh = &g_f1Hi[((size_t)b * NPTS2 + i) * 128];
    const uint16_t* fl = &g_f1Lo[((size_t)b * NPTS2 + i) * 128];
#pragma unroll
    for (int c2 = lane; c2 < 128; c2 += 32) {
        oh[3 + c2] = fh[c2];
        ol[3 + c2] = fl[c2];
    }
}

// ============================================================================
// HMMA bf16x3 GEMM, cp.async 3-stage pipeline, split-bf16 in/out.
// C = relu(A @ W^T + bias); optional max-pool over POOL rows.
// A: hi/lo bf16 planes [M, K] (K % 16 == 0, M % 128 == 0). W: hi/lo [N, K].
// Output: split bf16 planes (OUTFP32=0) or fp32 (OUTFP32=1, pooled only).
// ============================================================================
template <int BN, int POOL, int OUTFP32>
__global__ void __launch_bounds__(256) k_mgemm(const uint16_t* __restrict__ Ahi,
                                               const uint16_t* __restrict__ Alo,
                                               const uint16_t* __restrict__ Whi,
                                               const uint16_t* __restrict__ Wlo,
                                               const float* __restrict__ bias,
                                               float* __restrict__ Cf,
                                               uint16_t* __restrict__ Chi,
                                               uint16_t* __restrict__ Clo,
                                               int Mm, int Nn, int Kk) {
    constexpr int WR = (BN == 128) ? 2 : 4;
    constexpr int WC = 8 / WR;
    constexpr int WM = 128 / WR;
    constexpr int WN = BN / WC;
    constexpr int MA = WM / 16;
    constexpr int NA = WN / 8;
    constexpr int ASZ = 128 * 48;
    constexpr int BSZ = BN * 48;
    constexpr int STG = 2 * ASZ + 2 * BSZ;
    constexpr int STAGES = 3;

    extern __shared__ __align__(16) char sm[];
    uint32_t sb = smem_u32(sm);
    int t = threadIdx.x, lane = t & 31, wid = t >> 5;
    int wrow = wid / WC, wcol = wid % WC;
    int row0 = blockIdx.y * 128, col0 = blockIdx.x * BN;

    int arow = t >> 1, half = t & 1;
    const uint16_t* gAhi = Ahi + (size_t)(row0 + arow) * Kk + half * 8;
    const uint16_t* gAlo = Alo + (size_t)(row0 + arow) * Kk + half * 8;
    bool bact = arow < BN;
    const uint16_t* gWhi = Whi + (size_t)(col0 + arow) * Kk + half * 8;
    const uint16_t* gWlo = Wlo + (size_t)(col0 + arow) * Kk + half * 8;
    uint32_t dA = sb + arow * 48 + half * 16;
    uint32_t dB = sb + 2 * ASZ + arow * 48 + half * 16;

    int nch = Kk / 16;

#define PREFETCH(CH)                                                                        \
    {                                                                                       \
        int _c = (CH);                                                                      \
        if (_c < nch) {                                                                     \
            uint32_t so = (_c % STAGES) * STG;                                              \
            size_t ko = (size_t)_c * 16;                                                    \
            asm volatile("cp.async.cg.shared.global [%0], [%1], 16;" ::"r"(dA + so),        \
                         "l"(gAhi + ko));                                                   \
            asm volatile("cp.async.cg.shared.global [%0], [%1], 16;" ::"r"(dA + so + ASZ),  \
                         "l"(gAlo + ko));                                                   \
            if (bact) {                                                                     \
                asm volatile("cp.async.cg.shared.global [%0], [%1], 16;" ::"r"(dB + so),    \
                             "l"(gWhi + ko));                                               \
                asm volatile("cp.async.cg.shared.global [%0], [%1], 16;" ::"r"(              \
                                 dB + so + BSZ),                                            \
                             "l"(gWlo + ko));                                               \
            }                                                                               \
        }                                                                                   \
        asm volatile("cp.async.commit_group;");                                             \
    }

    PREFETCH(0);
    PREFETCH(1);

    int lro = (lane & 7) + ((lane >> 3) & 1) * 8;
    int hob = (lane >> 4) * 16;
    uint32_t bAhi[MA], bB[2];
#pragma unroll
    for (int ma = 0; ma < MA; ma++)
        bAhi[ma] = sb + (wrow * WM + ma * 16 + lro) * 48 + hob;
#pragma unroll
    for (int p = 0; p < 2; p++)
        bB[p] = sb + 2 * ASZ + (wcol * WN + p * 16 + lro) * 48 + hob;

    float acc[MA][NA][4];
#pragma unroll
    for (int ma = 0; ma < MA; ma++)
#pragma unroll
        for (int na = 0; na < NA; na++)
#pragma unroll
            for (int q = 0; q < 4; q++) acc[ma][na][q] = 0.f;

    for (int ch = 0; ch < nch; ch++) {
        asm volatile("cp.async.wait_group 1;");
        __syncthreads();
        PREFETCH(ch + 2);
        uint32_t so = (ch % STAGES) * STG;

        uint32_t ah[MA][4], al[MA][4], bh[2][4], bl[2][4];
#pragma unroll
        for (int ma = 0; ma < MA; ma++) {
            ldmx4(ah[ma], bAhi[ma] + so);
            ldmx4(al[ma], bAhi[ma] + so + ASZ);
        }
#pragma unroll
        for (int p = 0; p < 2; p++) {
            ldmx4(bh[p], bB[p] + so);
            ldmx4(bl[p], bB[p] + so + BSZ);
        }
#pragma unroll
        for (int ma = 0; ma < MA; ma++)
#pragma unroll
            for (int na = 0; na < NA; na++) {
                uint32_t bbh[2] = {bh[na >> 1][na & 1], bh[na >> 1][(na & 1) + 2]};
                uint32_t bbl[2] = {bl[na >> 1][na & 1], bl[na >> 1][(na & 1) + 2]};
                mma16816(acc[ma][na], ah[ma], bbh);
                mma16816(acc[ma][na], ah[ma], bbl);
                mma16816(acc[ma][na], al[ma], bbh);
            }
        __syncthreads();
    }
#undef PREFETCH

    int tg = lane >> 2, t4 = lane & 3;

    if (POOL == 0) {
#pragma unroll
        for (int ma = 0; ma < MA; ma++)
#pragma unroll
            for (int na = 0; na < NA; na++) {
                int cb = col0 + wcol * WN + na * 8 + t4 * 2;
                float b0 = bias[cb], b1 = bias[cb + 1];
#pragma unroll
                for (int h = 0; h < 2; h++) {
                    int r = row0 + wrow * WM + ma * 16 + tg + h * 8;
                    float v0 = fmaxf(acc[ma][na][h * 2 + 0] + b0, 0.f);
                    float v1 = fmaxf(acc[ma][na][h * 2 + 1] + b1, 0.f);
                    uint32_t ph, pl;
                    split2pack(v0, v1, ph, pl);
                    size_t off = (size_t)r * Nn + cb;
                    *(uint32_t*)(Chi + off) = ph;
                    *(uint32_t*)(Clo + off) = pl;
                }
            }
    } else {
        const int NG = 128 / POOL;
        int* red = (int*)(sm + STAGES * STG);
        for (int i = t; i < NG * BN; i += 256) red[i] = 0;
        __syncthreads();
#pragma unroll
        for (int ma = 0; ma < MA; ma++)
#pragma unroll
            for (int na = 0; na < NA; na++) {
                int cb = wcol * WN + na * 8 + t4 * 2;
                float b0 = bias[col0 + cb], b1 = bias[col0 + cb + 1];
#pragma unroll
                for (int h = 0; h < 2; h++) {
                    int rt = wrow * WM + ma * 16 + tg + h * 8;
                    int g = rt / POOL;
                    float v0 = fmaxf(acc[ma][na][h * 2 + 0] + b0, 0.f);
                    float v1 = fmaxf(acc[ma][na][h * 2 + 1] + b1, 0.f);
                    atomicMax(&red[g * BN + cb], __float_as_int(v0));
                    atomicMax(&red[g * BN + cb + 1], __float_as_int(v1));
                }
            }
        __syncthreads();
        for (int i = t; i < NG * BN; i += 256) {
            int g = i / BN, lc = i % BN;
            float v = __int_as_float(red[i]);
            size_t off = (size_t)(row0 / POOL + g) * Nn + col0 + lc;
            if (OUTFP32) {
                Cf[off] = v;
            } else {
                uint16_t h, l;
                split1(v, h, l);
                Chi[off] = h;
                Clo[off] = l;
            }
        }
    }
}

// ---------------- SIMT f32x2 GEMM (tiny glob layers) ----------------
__global__ void __launch_bounds__(256, 2) k_gemm2(const float* __restrict__ A,
                                                  const float* __restrict__ W,
                                                  const float* __restrict__ bias,
                                                  float* __restrict__ C,
                                                  int Mm, int Nn, int Kk, int relu) {
    __shared__ float As2[2][16][256];
    __shared__ float Bs[2][16][128];
    int t = threadIdx.x;
    int tx = t & 15, ty = t >> 4;
    int row0 = blockIdx.y * 128, col0 = blockIdx.x * 128;
    int lrow = t >> 1;
    int lk = (t & 1) * 8;
    bool aok = (row0 + lrow) < Mm;
    bool bok = (col0 + lrow) < Nn;
    const float* Ap = A + (size_t)(row0 + lrow) * Kk;
    const float* Wp = W + (size_t)(col0 + lrow) * Kk;

    unsigned long long acc[8][4];
#pragma unroll
    for (int i = 0; i < 8; i++)
#pragma unroll
        for (int j = 0; j < 4; j++) acc[i][j] = 0ull;

    int nchunks = (Kk + 15) / 16;
    {
        float av[8], bv[8];
#pragma unroll
        for (int q = 0; q < 8; q++) {
            int k = lk + q;
            av[q] = (aok && k < Kk) ? Ap[k] : 0.f;
            bv[q] = (bok && k < Kk) ? Wp[k] : 0.f;
        }
#pragma unroll
        for (int q = 0; q < 8; q++) {
            *(float2*)&As2[0][lk + q][2 * lrow] = make_float2(av[q], av[q]);
            Bs[0][lk + q][lrow] = bv[q];
        }
    }
    __syncthreads();

    for (int c = 0; c < nchunks; c++) {
        int buf = c & 1;
        float av[8], bv[8];
        bool more = (c + 1) < nchunks;
        if (more) {
            int k0 = (c + 1) * 16;
#pragma unroll
            for (int q = 0; q < 8; q++) {
                int k = k0 + lk + q;
                av[q] = (aok && k < Kk) ? Ap[k] : 0.f;
                bv[q] = (bok && k < Kk) ? Wp[k] : 0.f;
            }
        }
#pragma unroll
        for (int kk = 0; kk < 16; kk++) {
            const float* arow = As2[buf][kk];
            const float* brow = Bs[buf][kk];
            ulonglong2 aA = *(const ulonglong2*)(arow + ty * 8);
            ulonglong2 aB = *(const ulonglong2*)(arow + ty * 8 + 4);
            ulonglong2 aC = *(const ulonglong2*)(arow + 128 + ty * 8);
            ulonglong2 aD = *(const ulonglong2*)(arow + 128 + ty * 8 + 4);
            ulonglong2 b01 = *(const ulonglong2*)(brow + tx * 4);
            ulonglong2 b23 = *(const ulonglong2*)(brow + 64 + tx * 4);
            unsigned long long ar[8] = {aA.x, aA.y, aB.x, aB.y, aC.x, aC.y, aD.x, aD.y};
            unsigned long long br[4] = {b01.x, b01.y, b23.x, b23.y};
#pragma unroll
            for (int i = 0; i < 8; i++)
#pragma unroll
                for (int j = 0; j < 4; j++)
                    asm("fma.rn.f32x2 %0, %1, %2, %0;" : "+l"(acc[i][j]) : "l"(ar[i]), "l"(br[j]));
        }
        if (more) {
            int nb = buf ^ 1;
#pragma unroll
            for (int q = 0; q < 8; q++) {
                *(float2*)&As2[nb][lk + q][2 * lrow] = make_float2(av[q], av[q]);
                Bs[nb][lk + q][lrow] = bv[q];
            }
        }
        __syncthreads();
    }

#pragma unroll
    for (int blk = 0; blk < 2; blk++) {
#pragma unroll
        for (int i = 0; i < 4; i++) {
            int r = row0 + blk * 64 + ty * 4 + i;
            if (r >= Mm) continue;
#pragma unroll
            for (int jp = 0; jp < 4; jp++) {
                float2 v;
                asm("mov.b64 {%0, %1}, %2;" : "=f"(v.x), "=f"(v.y) : "l"(acc[blk * 4 + i][jp]));
                int cc = col0 + (jp >> 1) * 64 + tx * 4 + (jp & 1) * 2;
                if (cc < Nn) {
                    float x = v.x + bias[cc];
                    if (relu) x = fmaxf(x, 0.f);
                    C[(size_t)r * Nn + cc] = x;
                }
                if (cc + 1 < Nn) {
                    float x = v.y + bias[cc + 1];
                    if (relu) x = fmaxf(x, 0.f);
                    C[(size_t)r * Nn + cc + 1] = x;
                }
            }
        }
    }
}

// ---------------- host ----------------
static void* sym_addr(const void* sym) {
    void* p = nullptr;
    cudaGetSymbolAddress(&p, sym);
    return p;
}

static inline void gemm_s(const float* A, const float* W, const float* b, float* C,
                          int M, int N, int K, int relu) {
    dim3 grid((N + 127) / 128, (M + 127) / 128);
    k_gemm2<<<grid, 256>>>(A, W, b, C, M, N, K, relu);
}

template <int BN, int POOL, int OUTFP32>
static inline void gemm_t(const uint16_t* Ahi, const uint16_t* Alo,
                          const uint16_t* Whi, const uint16_t* Wlo,
                          const float* bias, float* Cf, uint16_t* Chi, uint16_t* Clo,
                          int M, int N, int K) {
    constexpr int SMEM = (2 * (128 * 48) + 2 * (BN * 48)) * 3 + 2048;
    static bool cfg = false;
    if (!cfg) {
        cudaFuncSetAttribute(k_mgemm<BN, POOL, OUTFP32>,
                             cudaFuncAttributeMaxDynamicSharedMemorySize, SMEM);
        cfg = true;
    }
    dim3 grid(N / BN, M / 128);
    k_mgemm<BN, POOL, OUTFP32><<<grid, 256, SMEM>>>(Ahi, Alo, Whi, Wlo, bias, Cf, Chi, Clo, M, N, K);
}

extern "C" void kernel_launch(void* const* d_in, const int* in_sizes, int n_in,
                              void* d_out, int out_size) {
    const float* pts = (const float*)d_in[0];
    const float* sa1w0 = (const float*)d_in[1];  const float* sa1b0 = (const float*)d_in[2];
    const float* sa1w1 = (const float*)d_in[3];  const float* sa1b1 = (const float*)d_in[4];
    const float* sa1w2 = (const float*)d_in[5];  const float* sa1b2 = (const float*)d_in[6];
    const float* sa2w0 = (const float*)d_in[7];  const float* sa2b0 = (const float*)d_in[8];
    const float* sa2w1 = (const float*)d_in[9];  const float* sa2b1 = (const float*)d_in[10];
    const float* sa2w2 = (const float*)d_in[11]; const float* sa2b2 = (const float*)d_in[12];
    const float* locw0 = (const float*)d_in[13]; const float* locb0 = (const float*)d_in[14];
    const float* locw1 = (const float*)d_in[15]; const float* locb1 = (const float*)d_in[16];
    const float* locw2 = (const float*)d_in[17]; const float* locb2 = (const float*)d_in[18];
    const float* glow0 = (const float*)d_in[19]; const float* glob0 = (const float*)d_in[20];
    const float* glow1 = (const float*)d_in[21]; const float* glob1 = (const float*)d_in[22];
    const float* clsw  = (const float*)d_in[23]; const float* clsb  = (const float*)d_in[24];
    float* out = (float*)d_out;

    float* xyz   = (float*)sym_addr(g_xyz);
    float* nx1   = (float*)sym_addr(g_newxyz1);
    float* nx2   = (float*)sym_addr(g_newxyz2);
    int*   ball1 = (int*)  sym_addr(g_ball1);
    int*   ball2 = (int*)  sym_addr(g_ball2);
    uint16_t* whi = (uint16_t*)sym_addr(g_whi);
    uint16_t* wlo = (uint16_t*)sym_addr(g_wlo);
    uint16_t* grpHi = (uint16_t*)sym_addr(g_grpHi);
    uint16_t* grpLo = (uint16_t*)sym_addr(g_grpLo);
    uint16_t* aHi = (uint16_t*)sym_addr(g_aHi);
    uint16_t* aLo = (uint16_t*)sym_addr(g_aLo);
    uint16_t* bHi = (uint16_t*)sym_addr(g_bHi);
    uint16_t* bLo = (uint16_t*)sym_addr(g_bLo);
    uint16_t* f1Hi = (uint16_t*)sym_addr(g_f1Hi);
    uint16_t* f1Lo = (uint16_t*)sym_addr(g_f1Lo);
    uint16_t* f2Hi = (uint16_t*)sym_addr(g_f2Hi);
    uint16_t* f2Lo = (uint16_t*)sym_addr(g_f2Lo);
    float* pool = (float*)sym_addr(g_pool);
    float* gg1  = (float*)sym_addr(g_g1);
    float* gg2  = (float*)sym_addr(g_g2);

    const float R2_1 = (float)(0.2 * 0.2);
    const float R2_2 = (float)(0.4 * 0.4);

    // 0. weight split (K padded to x16)
    {
        struct { const float* s; int off, N, Kin, Kpad; } ws[] = {
            {sa1w0, OW0, 64, 3, 16},     {sa1w1, OW1, 64, 64, 64},
            {sa1w2, OW2, 128, 64, 64},   {sa2w0, OS0, 128, 131, 144},
            {sa2w1, OS1, 128, 128, 128}, {sa2w2, OS2, 256, 128, 128},
            {locw0, OL0, 256, 256, 256}, {locw1, OL1, 512, 256, 256},
            {locw2, OL2, 1024, 512, 512},
        };
        for (auto& w : ws) {
            int n = w.N * w.Kpad;
            k_wsplit<<<(n + 255) / 256, 256>>>(w.s, whi + w.off, wlo + w.off, w.N, w.Kin, w.Kpad);
        }
    }

    // 1. transpose
    k_transpose<<<(BATCH * 3 * NPTS1 + 255) / 256, 256>>>(pts);

    // 2. SA1
    k_fps<8, NPTS1, M1><<<BATCH, 1024>>>(xyz, nx1);
    k_ballquery<NPTS1, M1, KNN1><<<(BATCH * M1) / 8, 256>>>(xyz, nx1, R2_1, ball1);
    k_group1s<<<(BATCH * M1 * KNN1 + 255) / 256, 256>>>();
    gemm_t<64, 0, 0>(grpHi, grpLo, whi + OW0, wlo + OW0, sa1b0, nullptr, aHi, aLo,
                     BATCH * M1 * KNN1, 64, 16);
    gemm_t<64, 0, 0>(aHi, aLo, whi + OW1, wlo + OW1, sa1b1, nullptr, bHi, bLo,
                     BATCH * M1 * KNN1, 64, 64);
    gemm_t<128, KNN1, 0>(bHi, bLo, whi + OW2, wlo + OW2, sa1b2, nullptr, f1Hi, f1Lo,
                         BATCH * M1 * KNN1, 128, 64);

    // 3. SA2
    k_fps<1, NPTS2, M2><<<BATCH, 512>>>(nx1, nx2);
    k_ballquery<NPTS2, M2, KNN2><<<(BATCH * M2) / 8, 256>>>(nx1, nx2, R2_2, ball2);
    k_group2s<<<(BATCH * M2 * KNN2 * 32 + 255) / 256, 256>>>();
    gemm_t<128, 0, 0>(grpHi, grpLo, whi + OS0, wlo + OS0, sa2b0, nullptr, aHi, aLo,
                      BATCH * M2 * KNN2, 128, 144);
    gemm_t<128, 0, 0>(aHi, aLo, whi + OS1, wlo + OS1, sa2b1, nullptr, bHi, bLo,
                      BATCH * M2 * KNN2, 128, 128);
    gemm_t<128, KNN2, 0>(bHi, bLo, whi + OS2, wlo + OS2, sa2b2, nullptr, f2Hi, f2Lo,
                         BATCH * M2 * KNN2, 256, 128);

    // 4. loc MLP + global max-pool
    gemm_t<128, 0, 0>(f2Hi, f2Lo, whi + OL0, wlo + OL0, locb0, nullptr, aHi, aLo,
                      BATCH * M2, 256, 256);
    gemm_t<128, 0, 0>(aHi, aLo, whi + OL1, wlo + OL1, locb1, nullptr, bHi, bLo,
                      BATCH * M2, 512, 256);
    gemm_t<128, 128, 1>(bHi, bLo, whi + OL2, wlo + OL2, locb2, pool, nullptr, nullptr,
                        BATCH * M2, 1024, 512);

    // 5. global MLP (tiny; SIMT)
    gemm_s(pool, glow0, glob0, gg1, BATCH, 512, 1024, 1);
    gemm_s(gg1,  glow1, glob1, gg2, BATCH, 256, 512, 1);
    gemm_s(gg2,  clsw,  clsb,  out, BATCH, 40, 256, 0);
}

// round 13
// speedup vs baseline: 1.5641x; 1.5641x over previous
#include <cuda_runtime.h>
#include <cuda_bf16.h>
#include <cstdint>
#include <cstddef>

#define BATCH 32
#define NPTS1 8192
#define M1 512
#define KNN1 32
#define M2 128
#define KNN2 64
#define NPTS2 512

// ---------------- scratch (static device globals) ----------------
__device__ float g_xyz[BATCH * NPTS1 * 3];
__device__ float g_newxyz1[BATCH * M1 * 3];
__device__ float g_newxyz2[BATCH * M2 * 3];
__device__ int   g_ball1[BATCH * M1 * KNN1];
__device__ int   g_ball2[BATCH * M2 * KNN2];

// split bf16 planes
__device__ uint16_t g_whi[801792];
__device__ uint16_t g_wlo[801792];
__device__ uint16_t g_grpHi[262144 * 144];
__device__ uint16_t g_grpLo[262144 * 144];
__device__ uint16_t g_aHi[524288 * 64];
__device__ uint16_t g_aLo[524288 * 64];
__device__ uint16_t g_bHi[524288 * 64];
__device__ uint16_t g_bLo[524288 * 64];
__device__ uint16_t g_f1Hi[16384 * 128];
__device__ uint16_t g_f1Lo[16384 * 128];
__device__ uint16_t g_f2Hi[4096 * 256];
__device__ uint16_t g_f2Lo[4096 * 256];

__device__ float g_pool[BATCH * 1024];
__device__ float g_g1[BATCH * 512];
__device__ float g_g2[BATCH * 256];

// weight plane offsets (elements), K padded to multiple of 16
#define OW0 0        // 64 x 16   (K=3 padded)
#define OW1 1024     // 64 x 64
#define OW2 5120     // 128 x 64
#define OS0 13312    // 128 x 144 (K=131 padded)
#define OS1 31744    // 128 x 128
#define OS2 48128    // 256 x 128
#define OL0 80896    // 256 x 256
#define OL1 146432   // 512 x 256
#define OL2 277504   // 1024 x 512

// ---------------- helpers ----------------
__device__ __forceinline__ uint32_t smem_u32(const void* p) {
    uint32_t a;
    asm("{ .reg .u64 t; cvta.to.shared.u64 t, %1; cvt.u32.u64 %0, t; }" : "=r"(a) : "l"(p));
    return a;
}
__device__ __forceinline__ void ldmx4(uint32_t* r, uint32_t a) {
    asm volatile("ldmatrix.sync.aligned.m8n8.x4.shared.b16 {%0,%1,%2,%3}, [%4];"
                 : "=r"(r[0]), "=r"(r[1]), "=r"(r[2]), "=r"(r[3]) : "r"(a));
}
__device__ __forceinline__ void mma16816(float* c, const uint32_t* a, const uint32_t* b) {
    asm volatile("mma.sync.aligned.m16n8k16.row.col.f32.bf16.bf16.f32 "
                 "{%0,%1,%2,%3}, {%4,%5,%6,%7}, {%8,%9}, {%0,%1,%2,%3};"
                 : "+f"(c[0]), "+f"(c[1]), "+f"(c[2]), "+f"(c[3])
                 : "r"(a[0]), "r"(a[1]), "r"(a[2]), "r"(a[3]), "r"(b[0]), "r"(b[1]));
}
__device__ __forceinline__ uint32_t pack_bf(__nv_bfloat16 a, __nv_bfloat16 b) {
    return ((uint32_t)__bfloat16_as_ushort(b) << 16) | __bfloat16_as_ushort(a);
}
__device__ __forceinline__ void split1(float v, uint16_t& h, uint16_t& l) {
    __nv_bfloat16 hb = __float2bfloat16(v);
    h = __bfloat16_as_ushort(hb);
    l = __bfloat16_as_ushort(__float2bfloat16(v - __bfloat162float(hb)));
}
__device__ __forceinline__ void split2pack(float v0, float v1, uint32_t& ph, uint32_t& pl) {
    __nv_bfloat16 h0 = __float2bfloat16(v0), h1 = __float2bfloat16(v1);
    __nv_bfloat16 l0 = __float2bfloat16(v0 - __bfloat162float(h0));
    __nv_bfloat16 l1 = __float2bfloat16(v1 - __bfloat162float(h1));
    ph = pack_bf(h0, h1);
    pl = pack_bf(l0, l1);
}

// ---------------- transpose ----------------
__global__ void k_transpose(const float* __restrict__ pts) {
    int idx = blockIdx.x * blockDim.x + threadIdx.x;
    if (idx >= BATCH * 3 * NPTS1) return;
    int b = idx / (3 * NPTS1);
    int r = idx % (3 * NPTS1);
    int c = r / NPTS1;
    int n = r % NPTS1;
    g_xyz[(b * NPTS1 + n) * 3 + c] = pts[idx];
}

// ---------------- weight split: src[N,Kin] fp32 -> hi/lo[N,Kpad] bf16 ----------------
__global__ void k_wsplit(const float* __restrict__ src, uint16_t* __restrict__ hi,
                         uint16_t* __restrict__ lo, int N, int Kin, int Kpad) {
    int i = blockIdx.x * blockDim.x + threadIdx.x;
    if (i >= N * Kpad) return;
    int r = i / Kpad, k = i % Kpad;
    float v = (k < Kin) ? src[r * Kin + k] : 0.f;
    split1(v, hi[i], lo[i]);
}

// ---------------- farthest point sampling ----------------
template <int P, int NP, int MSEL>
__global__ void k_fps(const float* __restrict__ xyz, float* __restrict__ new_xyz) {
    int b = blockIdx.x, tid = threadIdx.x, T = blockDim.x;
    float px[P], py[P], pz[P], pd[P];
#pragma unroll
    for (int j = 0; j < P; j++) {
        int i = j * T + tid;
        const float* p = &xyz[(b * NP + i) * 3];
        px[j] = p[0]; py[j] = p[1]; pz[j] = p[2];
        pd[j] = 1e10f;
    }
    __shared__ float s_cx, s_cy, s_cz;
    __shared__ float s_val[32];
    __shared__ int   s_idx[32];
    if (tid == 0) {
        const float* p = &xyz[(size_t)b * NP * 3];
        s_cx = p[0]; s_cy = p[1]; s_cz = p[2];
        float* o = &new_xyz[(size_t)b * MSEL * 3];
        o[0] = p[0]; o[1] = p[1]; o[2] = p[2];
    }
    __syncthreads();
    int nw = T >> 5;
    for (int it = 1; it < MSEL; it++) {
        float cx = s_cx, cy = s_cy, cz = s_cz;
        float bv = -1.0f; int bi = NP;
#pragma unroll
        for (int j = 0; j < P; j++) {
            int i = j * T + tid;
            float dx = px[j] - cx, dy = py[j] - cy, dz = pz[j] - cz;
            float d = fmaf(dz, dz, fmaf(dy, dy, dx * dx));
            d = fminf(pd[j], d);
            pd[j] = d;
            if (d > bv || (d == bv && i < bi)) { bv = d; bi = i; }
        }
#pragma unroll
        for (int off = 16; off > 0; off >>= 1) {
            float ov = __shfl_down_sync(0xffffffffu, bv, off);
            int   oi = __shfl_down_sync(0xffffffffu, bi, off);
            if (ov > bv || (ov == bv && oi < bi)) { bv = ov; bi = oi; }
        }
        int w = tid >> 5;
        if ((tid & 31) == 0) { s_val[w] = bv; s_idx[w] = bi; }
        __syncthreads();
        if (w == 0) {
            int lane = tid & 31;
            bv = (lane < nw) ? s_val[lane] : -2.0f;
            bi = (lane < nw) ? s_idx[lane] : NP;
#pragma unroll
            for (int off = 16; off > 0; off >>= 1) {
                float ov = __shfl_down_sync(0xffffffffu, bv, off);
                int   oi = __shfl_down_sync(0xffffffffu, bi, off);
                if (ov > bv || (ov == bv && oi < bi)) { bv = ov; bi = oi; }
            }
            if (lane == 0) {
                const float* p = &xyz[((size_t)b * NP + bi) * 3];
                s_cx = p[0]; s_cy = p[1]; s_cz = p[2];
                float* o = &new_xyz[((size_t)b * MSEL + it) * 3];
                o[0] = p[0]; o[1] = p[1]; o[2] = p[2];
            }
        }
        __syncthreads();
    }
}

// ---------------- ball query ----------------
template <int NP, int MSEL, int KQ>
__global__ void k_ballquery(const float* __restrict__ xyz, const float* __restrict__ cent,
                            float R2, int* __restrict__ out) {
    int gw = (blockIdx.x * blockDim.x + threadIdx.x) >> 5;
    int lane = threadIdx.x & 31;
    if (gw >= BATCH * MSEL) return;
    int b = gw / MSEL, m = gw % MSEL;
    const float* cp = &cent[((size_t)b * MSEL + m) * 3];
    float cx = cp[0], cy = cp[1], cz = cp[2];
    const float* xb = &xyz[(size_t)b * NP * 3];
    int* o = &out[((size_t)b * MSEL + m) * KQ];
    int cnt = 0, first = -1;
#pragma unroll 4
    for (int base = 0; base < NP; base += 32) {
        int i = base + lane;
        const float* p = &xb[i * 3];
        float dx = p[0] - cx, dy = p[1] - cy, dz = p[2] - cz;
        float d = fmaf(dz, dz, fmaf(dy, dy, dx * dx));
        bool valid = d < R2;
        unsigned mk = __ballot_sync(0xffffffffu, valid);
        if (first < 0 && mk) first = base + __ffs(mk) - 1;
        int pos = cnt + __popc(mk & ((1u << lane) - 1u));
        if (valid && pos < KQ) o[pos] = i;
        cnt += __popc(mk);
    }
    if (cnt > KQ) cnt = KQ;
    for (int p = cnt + lane; p < KQ; p += 32) o[p] = first;
}

// ---------------- grouping: SA1 -> grp planes [524288, 16] bf16 hi/lo ----------------
__global__ void k_group1s() {
    int r = blockIdx.x * blockDim.x + threadIdx.x;
    if (r >= BATCH * M1 * KNN1) return;
    int g = r / KNN1;
    int b = g / M1;
    int i = g_ball1[r];
    const float* p = &g_xyz[((size_t)b * NPTS1 + i) * 3];
    const float* c = &g_newxyz1[(size_t)g * 3];
    float d0 = p[0] - c[0], d1 = p[1] - c[1], d2 = p[2] - c[2];
    uint32_t ph0, pl0, ph1, pl1;
    split2pack(d0, d1, ph0, pl0);
    split2pack(d2, 0.f, ph1, pl1);
    uint4 qh = make_uint4(ph0, ph1, 0u, 0u);
    uint4 ql = make_uint4(pl0, pl1, 0u, 0u);
    uint4 z = make_uint4(0u, 0u, 0u, 0u);
    ((uint4*)g_grpHi)[(size_t)r * 2] = qh;
    ((uint4*)g_grpHi)[(size_t)r * 2 + 1] = z;
    ((uint4*)g_grpLo)[(size_t)r * 2] = ql;
    ((uint4*)g_grpLo)[(size_t)r * 2 + 1] = z;
}

// ---------------- grouping: SA2 -> grp planes [262144, 144] bf16 hi/lo ----------------
__global__ void k_group2s() {
    int gw = (blockIdx.x * blockDim.x + threadIdx.x) >> 5;
    int lane = threadIdx.x & 31;
    if (gw >= BATCH * M2 * KNN2) return;
    int g = gw / KNN2;
    int b = g / M2;
    int i = g_ball2[gw];
    uint16_t* oh = &g_grpHi[(size_t)gw * 144];
    uint16_t* ol = &g_grpLo[(size_t)gw * 144];
    const float* c = &g_newxyz2[(size_t)g * 3];
    const float* p = &g_newxyz1[((size_t)b * NPTS2 + i) * 3];
    if (lane < 3) {
        float d = p[lane] - c[lane];
        uint16_t h, l;
        split1(d, h, l);
        oh[lane] = h; ol[lane] = l;
    }
    if (lane >= 3 && lane < 16) {  // zero tail cols 131..143
        oh[128 + lane] = 0; ol[128 + lane] = 0;
    }
    const uint16_t* fh = &g_f1Hi[((size_t)b * NPTS2 + i) * 128];
    const uint16_t* fl = &g_f1Lo[((size_t)b * NPTS2 + i) * 128];
#pragma unroll
    for (int c2 = lane; c2 < 128; c2 += 32) {
        oh[3 + c2] = fh[c2];
        ol[3 + c2] = fl[c2];
    }
}

// ============================================================================
// HMMA bf16x3 GEMM, synchronous reg-staged loads, double-buffered smem,
// ONE __syncthreads per K-chunk. Split-bf16 in; split-bf16 or fp32 out.
// C = relu(A @ W^T + bias); optional max-pool over POOL rows.
// A: hi/lo planes [M, K] (K%16==0, M%128==0). W: hi/lo [N, K].
// ============================================================================
template <int BN, int POOL, int OUTFP32>
__global__ void __launch_bounds__(256) k_mgemm(const uint16_t* __restrict__ Ahi,
                                               const uint16_t* __restrict__ Alo,
                                               const uint16_t* __restrict__ Whi,
                                               const uint16_t* __restrict__ Wlo,
                                               const float* __restrict__ bias,
                                               float* __restrict__ Cf,
                                               uint16_t* __restrict__ Chi,
                                               uint16_t* __restrict__ Clo,
                                               int Mm, int Nn, int Kk) {
    constexpr int WR = (BN == 128) ? 2 : 4;
    constexpr int WC = 8 / WR;
    constexpr int WM = 128 / WR;
    constexpr int WN = BN / WC;
    constexpr int MA = WM / 16;
    constexpr int NA = WN / 8;
    constexpr int ASZ = 128 * 48;          // one bf16 plane of A rows (48B stride)
    constexpr int BSZ = BN * 48;
    constexpr int STG = 2 * ASZ + 2 * BSZ; // [Ahi][Alo][Bhi][Blo]

    extern __shared__ __align__(16) char sm[];
    uint32_t sb = smem_u32(sm);
    int t = threadIdx.x, lane = t & 31, wid = t >> 5;
    int wrow = wid / WC, wcol = wid % WC;
    int row0 = blockIdx.y * 128, col0 = blockIdx.x * BN;

    int arow = t >> 1, half = t & 1;
    const uint16_t* gAhi = Ahi + (size_t)(row0 + arow) * Kk + half * 8;
    const uint16_t* gAlo = Alo + (size_t)(row0 + arow) * Kk + half * 8;
    bool bact = arow < BN;
    const uint16_t* gWhi = Whi + (size_t)(col0 + arow) * Kk + half * 8;
    const uint16_t* gWlo = Wlo + (size_t)(col0 + arow) * Kk + half * 8;
    uint32_t stoff = (uint32_t)(arow * 48 + half * 16);

    int nch = Kk / 16;

    // prologue: chunk 0 -> stage 0
    {
        uint4 a0 = *(const uint4*)gAhi;
        uint4 a1 = *(const uint4*)gAlo;
        *(uint4*)(sm + stoff) = a0;
        *(uint4*)(sm + ASZ + stoff) = a1;
        if (bact) {
            uint4 b0 = *(const uint4*)gWhi;
            uint4 b1 = *(const uint4*)gWlo;
            *(uint4*)(sm + 2 * ASZ + stoff) = b0;
            *(uint4*)(sm + 2 * ASZ + BSZ + stoff) = b1;
        }
    }

    int lro = (lane & 7) + ((lane >> 3) & 1) * 8;
    int hob = (lane >> 4) * 16;
    uint32_t bAhi[MA], bB[2];
#pragma unroll
    for (int ma = 0; ma < MA; ma++)
        bAhi[ma] = sb + (wrow * WM + ma * 16 + lro) * 48 + hob;
#pragma unroll
    for (int p = 0; p < 2; p++)
        bB[p] = sb + 2 * ASZ + (wcol * WN + p * 16 + lro) * 48 + hob;

    float acc[MA][NA][4];
#pragma unroll
    for (int ma = 0; ma < MA; ma++)
#pragma unroll
        for (int na = 0; na < NA; na++)
#pragma unroll
            for (int q = 0; q < 4; q++) acc[ma][na][q] = 0.f;

    __syncthreads();

    for (int ch = 0; ch < nch; ch++) {
        uint32_t so = (uint32_t)(ch & 1) * STG;
        bool more = (ch + 1) < nch;
        uint4 na0, na1, nb0, nb1;
        if (more) {
            size_t ko = (size_t)(ch + 1) * 16;
            na0 = *(const uint4*)(gAhi + ko);
            na1 = *(const uint4*)(gAlo + ko);
            if (bact) {
                nb0 = *(const uint4*)(gWhi + ko);
                nb1 = *(const uint4*)(gWlo + ko);
            }
        }

        uint32_t ah[MA][4], al[MA][4], bh[2][4], bl[2][4];
#pragma unroll
        for (int ma = 0; ma < MA; ma++) {
            ldmx4(ah[ma], bAhi[ma] + so);
            ldmx4(al[ma], bAhi[ma] + so + ASZ);
        }
#pragma unroll
        for (int p = 0; p < 2; p++) {
            ldmx4(bh[p], bB[p] + so);
            ldmx4(bl[p], bB[p] + so + BSZ);
        }
#pragma unroll
        for (int ma = 0; ma < MA; ma++)
#pragma unroll
            for (int na = 0; na < NA; na++) {
                uint32_t bbh[2] = {bh[na >> 1][na & 1], bh[na >> 1][(na & 1) + 2]};
                uint32_t bbl[2] = {bl[na >> 1][na & 1], bl[na >> 1][(na & 1) + 2]};
                mma16816(acc[ma][na], ah[ma], bbh);
                mma16816(acc[ma][na], ah[ma], bbl);
                mma16816(acc[ma][na], al[ma], bbh);
            }

        if (more) {
            uint32_t so2 = (uint32_t)((ch + 1) & 1) * STG;
            *(uint4*)(sm + so2 + stoff) = na0;
            *(uint4*)(sm + so2 + ASZ + stoff) = na1;
            if (bact) {
                *(uint4*)(sm + so2 + 2 * ASZ + stoff) = nb0;
                *(uint4*)(sm + so2 + 2 * ASZ + BSZ + stoff) = nb1;
            }
        }
        __syncthreads();
    }

    int tg = lane >> 2, t4 = lane & 3;

    if (POOL == 0) {
#pragma unroll
        for (int ma = 0; ma < MA; ma++)
#pragma unroll
            for (int na = 0; na < NA; na++) {
                int cb = col0 + wcol * WN + na * 8 + t4 * 2;
                float b0 = bias[cb], b1 = bias[cb + 1];
#pragma unroll
                for (int h = 0; h < 2; h++) {
                    int r = row0 + wrow * WM + ma * 16 + tg + h * 8;
                    float v0 = fmaxf(acc[ma][na][h * 2 + 0] + b0, 0.f);
                    float v1 = fmaxf(acc[ma][na][h * 2 + 1] + b1, 0.f);
                    uint32_t ph, pl;
                    split2pack(v0, v1, ph, pl);
                    size_t off = (size_t)r * Nn + cb;
                    *(uint32_t*)(Chi + off) = ph;
                    *(uint32_t*)(Clo + off) = pl;
                }
            }
    } else {
        const int NG = 128 / POOL;
        int* red = (int*)(sm + 2 * STG);
        for (int i = t; i < NG * BN; i += 256) red[i] = 0;
        __syncthreads();
#pragma unroll
        for (int ma = 0; ma < MA; ma++)
#pragma unroll
            for (int na = 0; na < NA; na++) {
                int cb = wcol * WN + na * 8 + t4 * 2;
                float b0 = bias[col0 + cb], b1 = bias[col0 + cb + 1];
#pragma unroll
                for (int h = 0; h < 2; h++) {
                    int rt = wrow * WM + ma * 16 + tg + h * 8;
                    int g = rt / POOL;
                    float v0 = fmaxf(acc[ma][na][h * 2 + 0] + b0, 0.f);
                    float v1 = fmaxf(acc[ma][na][h * 2 + 1] + b1, 0.f);
                    atomicMax(&red[g * BN + cb], __float_as_int(v0));
                    atomicMax(&red[g * BN + cb + 1], __float_as_int(v1));
                }
            }
        __syncthreads();
        for (int i = t; i < NG * BN; i += 256) {
            int g = i / BN, lc = i % BN;
            float v = __int_as_float(red[i]);
            size_t off = (size_t)(row0 / POOL + g) * Nn + col0 + lc;
            if (OUTFP32) {
                Cf[off] = v;
            } else {
                uint16_t h, l;
                split1(v, h, l);
                Chi[off] = h;
                Clo[off] = l;
            }
        }
    }
}

// ---------------- SIMT f32x2 GEMM (tiny glob layers) ----------------
__global__ void __launch_bounds__(256, 2) k_gemm2(const float* __restrict__ A,
                                                  const float* __restrict__ W,
                                                  const float* __restrict__ bias,
                                                  float* __restrict__ C,
                                                  int Mm, int Nn, int Kk, int relu) {
    __shared__ float As2[2][16][256];
    __shared__ float Bs[2][16][128];
    int t = threadIdx.x;
    int tx = t & 15, ty = t >> 4;
    int row0 = blockIdx.y * 128, col0 = blockIdx.x * 128;
    int lrow = t >> 1;
    int lk = (t & 1) * 8;
    bool aok = (row0 + lrow) < Mm;
    bool bok = (col0 + lrow) < Nn;
    const float* Ap = A + (size_t)(row0 + lrow) * Kk;
    const float* Wp = W + (size_t)(col0 + lrow) * Kk;

    unsigned long long acc[8][4];
#pragma unroll
    for (int i = 0; i < 8; i++)
#pragma unroll
        for (int j = 0; j < 4; j++) acc[i][j] = 0ull;

    int nchunks = (Kk + 15) / 16;
    {
        float av[8], bv[8];
#pragma unroll
        for (int q = 0; q < 8; q++) {
            int k = lk + q;
            av[q] = (aok && k < Kk) ? Ap[k] : 0.f;
            bv[q] = (bok && k < Kk) ? Wp[k] : 0.f;
        }
#pragma unroll
        for (int q = 0; q < 8; q++) {
            *(float2*)&As2[0][lk + q][2 * lrow] = make_float2(av[q], av[q]);
            Bs[0][lk + q][lrow] = bv[q];
        }
    }
    __syncthreads();

    for (int c = 0; c < nchunks; c++) {
        int buf = c & 1;
        float av[8], bv[8];
        bool more = (c + 1) < nchunks;
        if (more) {
            int k0 = (c + 1) * 16;
#pragma unroll
            for (int q = 0; q < 8; q++) {
                int k = k0 + lk + q;
                av[q] = (aok && k < Kk) ? Ap[k] : 0.f;
                bv[q] = (bok && k < Kk) ? Wp[k] : 0.f;
            }
        }
#pragma unroll
        for (int kk = 0; kk < 16; kk++) {
            const float* arow = As2[buf][kk];
            const float* brow = Bs[buf][kk];
            ulonglong2 aA = *(const ulonglong2*)(arow + ty * 8);
            ulonglong2 aB = *(const ulonglong2*)(arow + ty * 8 + 4);
            ulonglong2 aC = *(const ulonglong2*)(arow + 128 + ty * 8);
            ulonglong2 aD = *(const ulonglong2*)(arow + 128 + ty * 8 + 4);
            ulonglong2 b01 = *(const ulonglong2*)(brow + tx * 4);
            ulonglong2 b23 = *(const ulonglong2*)(brow + 64 + tx * 4);
            unsigned long long ar[8] = {aA.x, aA.y, aB.x, aB.y, aC.x, aC.y, aD.x, aD.y};
            unsigned long long br[4] = {b01.x, b01.y, b23.x, b23.y};
#pragma unroll
            for (int i = 0; i < 8; i++)
#pragma unroll
                for (int j = 0; j < 4; j++)
                    asm("fma.rn.f32x2 %0, %1, %2, %0;" : "+l"(acc[i][j]) : "l"(ar[i]), "l"(br[j]));
        }
        if (more) {
            int nb = buf ^ 1;
#pragma unroll
            for (int q = 0; q < 8; q++) {
                *(float2*)&As2[nb][lk + q][2 * lrow] = make_float2(av[q], av[q]);
                Bs[nb][lk + q][lrow] = bv[q];
            }
        }
        __syncthreads();
    }

#pragma unroll
    for (int blk = 0; blk < 2; blk++) {
#pragma unroll
        for (int i = 0; i < 4; i++) {
            int r = row0 + blk * 64 + ty * 4 + i;
            if (r >= Mm) continue;
#pragma unroll
            for (int jp = 0; jp < 4; jp++) {
                float2 v;
                asm("mov.b64 {%0, %1}, %2;" : "=f"(v.x), "=f"(v.y) : "l"(acc[blk * 4 + i][jp]));
                int cc = col0 + (jp >> 1) * 64 + tx * 4 + (jp & 1) * 2;
                if (cc < Nn) {
                    float x = v.x + bias[cc];
                    if (relu) x = fmaxf(x, 0.f);
                    C[(size_t)r * Nn + cc] = x;
                }
                if (cc + 1 < Nn) {
                    float x = v.y + bias[cc + 1];
                    if (relu) x = fmaxf(x, 0.f);
                    C[(size_t)r * Nn + cc + 1] = x;
                }
            }
        }
    }
}

// ---------------- host ----------------
static void* sym_addr(const void* sym) {
    void* p = nullptr;
    cudaGetSymbolAddress(&p, sym);
    return p;
}

static inline void gemm_s(const float* A, const float* W, const float* b, float* C,
                          int M, int N, int K, int relu) {
    dim3 grid((N + 127) / 128, (M + 127) / 128);
    k_gemm2<<<grid, 256>>>(A, W, b, C, M, N, K, relu);
}

template <int BN, int POOL, int OUTFP32>
static inline void gemm_t(const uint16_t* Ahi, const uint16_t* Alo,
                          const uint16_t* Whi, const uint16_t* Wlo,
                          const float* bias, float* Cf, uint16_t* Chi, uint16_t* Clo,
                          int M, int N, int K) {
    constexpr int SMEM = 2 * (2 * (128 * 48) + 2 * (BN * 48)) + 2048;
    static bool cfg = false;
    if (!cfg) {
        cudaFuncSetAttribute(k_mgemm<BN, POOL, OUTFP32>,
                             cudaFuncAttributeMaxDynamicSharedMemorySize, SMEM);
        cfg = true;
    }
    dim3 grid(N / BN, M / 128);
    k_mgemm<BN, POOL, OUTFP32><<<grid, 256, SMEM>>>(Ahi, Alo, Whi, Wlo, bias, Cf, Chi, Clo, M, N, K);
}

extern "C" void kernel_launch(void* const* d_in, const int* in_sizes, int n_in,
                              void* d_out, int out_size) {
    const float* pts = (const float*)d_in[0];
    const float* sa1w0 = (const float*)d_in[1];  const float* sa1b0 = (const float*)d_in[2];
    const float* sa1w1 = (const float*)d_in[3];  const float* sa1b1 = (const float*)d_in[4];
    const float* sa1w2 = (const float*)d_in[5];  const float* sa1b2 = (const float*)d_in[6];
    const float* sa2w0 = (const float*)d_in[7];  const float* sa2b0 = (const float*)d_in[8];
    const float* sa2w1 = (const float*)d_in[9];  const float* sa2b1 = (const float*)d_in[10];
    const float* sa2w2 = (const float*)d_in[11]; const float* sa2b2 = (const float*)d_in[12];
    const float* locw0 = (const float*)d_in[13]; const float* locb0 = (const float*)d_in[14];
    const float* locw1 = (const float*)d_in[15]; const float* locb1 = (const float*)d_in[16];
    const float* locw2 = (const float*)d_in[17]; const float* locb2 = (const float*)d_in[18];
    const float* glow0 = (const float*)d_in[19]; const float* glob0 = (const float*)d_in[20];
    const float* glow1 = (const float*)d_in[21]; const float* glob1 = (const float*)d_in[22];
    const float* clsw  = (const float*)d_in[23]; const float* clsb  = (const float*)d_in[24];
    float* out = (float*)d_out;

    float* xyz   = (float*)sym_addr(g_xyz);
    float* nx1   = (float*)sym_addr(g_newxyz1);
    float* nx2   = (float*)sym_addr(g_newxyz2);
    int*   ball1 = (int*)  sym_addr(g_ball1);
    int*   ball2 = (int*)  sym_addr(g_ball2);
    uint16_t* whi = (uint16_t*)sym_addr(g_whi);
    uint16_t* wlo = (uint16_t*)sym_addr(g_wlo);
    uint16_t* grpHi = (uint16_t*)sym_addr(g_grpHi);
    uint16_t* grpLo = (uint16_t*)sym_addr(g_grpLo);
    uint16_t* aHi = (uint16_t*)sym_addr(g_aHi);
    uint16_t* aLo = (uint16_t*)sym_addr(g_aLo);
    uint16_t* bHi = (uint16_t*)sym_addr(g_bHi);
    uint16_t* bLo = (uint16_t*)sym_addr(g_bLo);
    uint16_t* f1Hi = (uint16_t*)sym_addr(g_f1Hi);
    uint16_t* f1Lo = (uint16_t*)sym_addr(g_f1Lo);
    uint16_t* f2Hi = (uint16_t*)sym_addr(g_f2Hi);
    uint16_t* f2Lo = (uint16_t*)sym_addr(g_f2Lo);
    float* pool = (float*)sym_addr(g_pool);
    float* gg1  = (float*)sym_addr(g_g1);
    float* gg2  = (float*)sym_addr(g_g2);

    const float R2_1 = (float)(0.2 * 0.2);
    const float R2_2 = (float)(0.4 * 0.4);

    // 0. weight split (K padded to x16)
    {
        struct { const float* s; int off, N, Kin, Kpad; } ws[] = {
            {sa1w0, OW0, 64, 3, 16},     {sa1w1, OW1, 64, 64, 64},
            {sa1w2, OW2, 128, 64, 64},   {sa2w0, OS0, 128, 131, 144},
            {sa2w1, OS1, 128, 128, 128}, {sa2w2, OS2, 256, 128, 128},
            {locw0, OL0, 256, 256, 256}, {locw1, OL1, 512, 256, 256},
            {locw2, OL2, 1024, 512, 512},
        };
        for (auto& w : ws) {
            int n = w.N * w.Kpad;
            k_wsplit<<<(n + 255) / 256, 256>>>(w.s, whi + w.off, wlo + w.off, w.N, w.Kin, w.Kpad);
        }
    }

    // 1. transpose
    k_transpose<<<(BATCH * 3 * NPTS1 + 255) / 256, 256>>>(pts);

    // 2. SA1
    k_fps<8, NPTS1, M1><<<BATCH, 1024>>>(xyz, nx1);
    k_ballquery<NPTS1, M1, KNN1><<<(BATCH * M1) / 8, 256>>>(xyz, nx1, R2_1, ball1);
    k_group1s<<<(BATCH * M1 * KNN1 + 255) / 256, 256>>>();
    gemm_t<64, 0, 0>(grpHi, grpLo, whi + OW0, wlo + OW0, sa1b0, nullptr, aHi, aLo,
                     BATCH * M1 * KNN1, 64, 16);
    gemm_t<64, 0, 0>(aHi, aLo, whi + OW1, wlo + OW1, sa1b1, nullptr, bHi, bLo,
                     BATCH * M1 * KNN1, 64, 64);
    gemm_t<128, KNN1, 0>(bHi, bLo, whi + OW2, wlo + OW2, sa1b2, nullptr, f1Hi, f1Lo,
                         BATCH * M1 * KNN1, 128, 64);

    // 3. SA2
    k_fps<1, NPTS2, M2><<<BATCH, 512>>>(nx1, nx2);
    k_ballquery<NPTS2, M2, KNN2><<<(BATCH * M2) / 8, 256>>>(nx1, nx2, R2_2, ball2);
    k_group2s<<<(BATCH * M2 * KNN2 * 32 + 255) / 256, 256>>>();
    gemm_t<128, 0, 0>(grpHi, grpLo, whi + OS0, wlo + OS0, sa2b0, nullptr, aHi, aLo,
                      BATCH * M2 * KNN2, 128, 144);
    gemm_t<128, 0, 0>(aHi, aLo, whi + OS1, wlo + OS1, sa2b1, nullptr, bHi, bLo,
                      BATCH * M2 * KNN2, 128, 128);
    gemm_t<128, KNN2, 0>(bHi, bLo, whi + OS2, wlo + OS2, sa2b2, nullptr, f2Hi, f2Lo,
                         BATCH * M2 * KNN2, 256, 128);

    // 4. loc MLP + global max-pool
    gemm_t<128, 0, 0>(f2Hi, f2Lo, whi + OL0, wlo + OL0, locb0, nullptr, aHi, aLo,
                      BATCH * M2, 256, 256);
    gemm_t<128, 0, 0>(aHi, aLo, whi + OL1, wlo + OL1, locb1, nullptr, bHi, bLo,
                      BATCH * M2, 512, 256);
    gemm_t<128, 128, 1>(bHi, bLo, whi + OL2, wlo + OL2, locb2, pool, nullptr, nullptr,
                        BATCH * M2, 1024, 512);

    // 5. global MLP (tiny; SIMT)
    gemm_s(pool, glow0, glob0, gg1, BATCH, 512, 1024, 1);
    gemm_s(gg1,  glow1, glob1, gg2, BATCH, 256, 512, 1);
    gemm_s(gg2,  clsw,  clsb,  out, BATCH, 40, 256, 0);
}

// round 16
// speedup vs baseline: 1.6384x; 1.0475x over previous
#include <cuda_runtime.h>
#include <cuda_bf16.h>
#include <cstdint>
#include <cstddef>

#define BATCH 32
#define NPTS1 8192
#define M1 512
#define KNN1 32
#define M2 128
#define KNN2 64
#define NPTS2 512

// ---------------- scratch (static device globals) ----------------
__device__ float g_xyz[BATCH * NPTS1 * 3];
__device__ float g_newxyz1[BATCH * M1 * 3];
__device__ float g_newxyz2[BATCH * M2 * 3];
__device__ int   g_ball1[BATCH * M1 * KNN1];
__device__ int   g_ball2[BATCH * M2 * KNN2];

// split bf16 planes
__device__ uint16_t g_whi[804864];
__device__ uint16_t g_wlo[804864];
__device__ uint16_t g_grpHi[262144 * 160];
__device__ uint16_t g_grpLo[262144 * 160];
__device__ uint16_t g_aHi[524288 * 64];
__device__ uint16_t g_aLo[524288 * 64];
__device__ uint16_t g_bHi[524288 * 64];
__device__ uint16_t g_bLo[524288 * 64];
__device__ uint16_t g_f1Hi[16384 * 128];
__device__ uint16_t g_f1Lo[16384 * 128];
__device__ uint16_t g_f2Hi[4096 * 256];
__device__ uint16_t g_f2Lo[4096 * 256];

__device__ float g_pool[BATCH * 1024];
__device__ float g_g1[BATCH * 512];
__device__ float g_g2[BATCH * 256];

// weight plane offsets (elements), K padded to multiple of 32
#define OW0 0        // 64 x 32
#define OW1 2048     // 64 x 64
#define OW2 6144     // 128 x 64
#define OS0 14336    // 128 x 160
#define OS1 34816    // 128 x 128
#define OS2 51200    // 256 x 128
#define OL0 83968    // 256 x 256
#define OL1 149504   // 512 x 256
#define OL2 280576   // 1024 x 512
#define WTOTAL 804864

// ---------------- helpers ----------------
__device__ __forceinline__ uint32_t smem_u32(const void* p) {
    uint32_t a;
    asm("{ .reg .u64 t; cvta.to.shared.u64 t, %1; cvt.u32.u64 %0, t; }" : "=r"(a) : "l"(p));
    return a;
}
__device__ __forceinline__ void ldmx4(uint32_t* r, uint32_t a) {
    asm volatile("ldmatrix.sync.aligned.m8n8.x4.shared.b16 {%0,%1,%2,%3}, [%4];"
                 : "=r"(r[0]), "=r"(r[1]), "=r"(r[2]), "=r"(r[3]) : "r"(a));
}
__device__ __forceinline__ void mma16816(float* c, const uint32_t* a, const uint32_t* b) {
    asm volatile("mma.sync.aligned.m16n8k16.row.col.f32.bf16.bf16.f32 "
                 "{%0,%1,%2,%3}, {%4,%5,%6,%7}, {%8,%9}, {%0,%1,%2,%3};"
                 : "+f"(c[0]), "+f"(c[1]), "+f"(c[2]), "+f"(c[3])
                 : "r"(a[0]), "r"(a[1]), "r"(a[2]), "r"(a[3]), "r"(b[0]), "r"(b[1]));
}
__device__ __forceinline__ uint32_t pack_bf(__nv_bfloat16 a, __nv_bfloat16 b) {
    return ((uint32_t)__bfloat16_as_ushort(b) << 16) | __bfloat16_as_ushort(a);
}
__device__ __forceinline__ void split1(float v, uint16_t& h, uint16_t& l) {
    __nv_bfloat16 hb = __float2bfloat16(v);
    h = __bfloat16_as_ushort(hb);
    l = __bfloat16_as_ushort(__float2bfloat16(v - __bfloat162float(hb)));
}
__device__ __forceinline__ void split2pack(float v0, float v1, uint32_t& ph, uint32_t& pl) {
    __nv_bfloat16 h0 = __float2bfloat16(v0), h1 = __float2bfloat16(v1);
    __nv_bfloat16 l0 = __float2bfloat16(v0 - __bfloat162float(h0));
    __nv_bfloat16 l1 = __float2bfloat16(v1 - __bfloat162float(h1));
    ph = pack_bf(h0, h1);
    pl = pack_bf(l0, l1);
}

// ---------------- transpose ----------------
__global__ void k_transpose(const float* __restrict__ pts) {
    int idx = blockIdx.x * blockDim.x + threadIdx.x;
    if (idx >= BATCH * 3 * NPTS1) return;
    int b = idx / (3 * NPTS1);
    int r = idx % (3 * NPTS1);
    int c = r / NPTS1;
    int n = r % NPTS1;
    g_xyz[(b * NPTS1 + n) * 3 + c] = pts[idx];
}

// ---------------- batched weight split ----------------
struct WSplitArgs {
    const float* src[9];
    int off[9];
    int N[9];
    int Kin[9];
    int Kpad[9];
};

__global__ void k_wsplit_all(WSplitArgs a, uint16_t* __restrict__ hi, uint16_t* __restrict__ lo) {
    int i = blockIdx.x * blockDim.x + threadIdx.x;
    if (i >= WTOTAL) return;
    int s = 0;
#pragma unroll
    for (int j = 1; j < 9; j++)
        if (i >= a.off[j]) s = j;
    int local = i - a.off[s];
    int kp = a.Kpad[s];
    int r = local / kp, k = local % kp;
    float v = (k < a.Kin[s]) ? a.src[s][r * a.Kin[s] + k] : 0.f;
    split1(v, hi[i], lo[i]);
}

// ---------------- farthest point sampling ----------------
template <int P, int NP, int MSEL>
__global__ void k_fps(const float* __restrict__ xyz, float* __restrict__ new_xyz) {
    int b = blockIdx.x, tid = threadIdx.x, T = blockDim.x;
    float px[P], py[P], pz[P], pd[P];
#pragma unroll
    for (int j = 0; j < P; j++) {
        int i = j * T + tid;
        const float* p = &xyz[(b * NP + i) * 3];
        px[j] = p[0]; py[j] = p[1]; pz[j] = p[2];
        pd[j] = 1e10f;
    }
    __shared__ float s_cx, s_cy, s_cz;
    __shared__ float s_val[32];
    __shared__ int   s_idx[32];
    if (tid == 0) {
        const float* p = &xyz[(size_t)b * NP * 3];
        s_cx = p[0]; s_cy = p[1]; s_cz = p[2];
        float* o = &new_xyz[(size_t)b * MSEL * 3];
        o[0] = p[0]; o[1] = p[1]; o[2] = p[2];
    }
    __syncthreads();
    int nw = T >> 5;
    for (int it = 1; it < MSEL; it++) {
        float cx = s_cx, cy = s_cy, cz = s_cz;
        float bv = -1.0f; int bi = NP;
#pragma unroll
        for (int j = 0; j < P; j++) {
            int i = j * T + tid;
            float dx = px[j] - cx, dy = py[j] - cy, dz = pz[j] - cz;
            float d = fmaf(dz, dz, fmaf(dy, dy, dx * dx));
            d = fminf(pd[j], d);
            pd[j] = d;
            if (d > bv || (d == bv && i < bi)) { bv = d; bi = i; }
        }
#pragma unroll
        for (int off = 16; off > 0; off >>= 1) {
            float ov = __shfl_down_sync(0xffffffffu, bv, off);
            int   oi = __shfl_down_sync(0xffffffffu, bi, off);
            if (ov > bv || (ov == bv && oi < bi)) { bv = ov; bi = oi; }
        }
        int w = tid >> 5;
        if ((tid & 31) == 0) { s_val[w] = bv; s_idx[w] = bi; }
        __syncthreads();
        if (w == 0) {
            int lane = tid & 31;
            bv = (lane < nw) ? s_val[lane] : -2.0f;
            bi = (lane < nw) ? s_idx[lane] : NP;
#pragma unroll
            for (int off = 16; off > 0; off >>= 1) {
                float ov = __shfl_down_sync(0xffffffffu, bv, off);
                int   oi = __shfl_down_sync(0xffffffffu, bi, off);
                if (ov > bv || (ov == bv && oi < bi)) { bv = ov; bi = oi; }
            }
            if (lane == 0) {
                const float* p = &xyz[((size_t)b * NP + bi) * 3];
                s_cx = p[0]; s_cy = p[1]; s_cz = p[2];
                float* o = &new_xyz[((size_t)b * MSEL + it) * 3];
                o[0] = p[0]; o[1] = p[1]; o[2] = p[2];
            }
        }
        __syncthreads();
    }
}

// ---------------- ball query ----------------
template <int NP, int MSEL, int KQ>
__global__ void k_ballquery(const float* __restrict__ xyz, const float* __restrict__ cent,
                            float R2, int* __restrict__ out) {
    int gw = (blockIdx.x * blockDim.x + threadIdx.x) >> 5;
    int lane = threadIdx.x & 31;
    if (gw >= BATCH * MSEL) return;
    int b = gw / MSEL, m = gw % MSEL;
    const float* cp = &cent[((size_t)b * MSEL + m) * 3];
    float cx = cp[0], cy = cp[1], cz = cp[2];
    const float* xb = &xyz[(size_t)b * NP * 3];
    int* o = &out[((size_t)b * MSEL + m) * KQ];
    int cnt = 0, first = -1;
#pragma unroll 4
    for (int base = 0; base < NP; base += 32) {
        int i = base + lane;
        const float* p = &xb[i * 3];
        float dx = p[0] - cx, dy = p[1] - cy, dz = p[2] - cz;
        float d = fmaf(dz, dz, fmaf(dy, dy, dx * dx));
        bool valid = d < R2;
        unsigned mk = __ballot_sync(0xffffffffu, valid);
        if (first < 0 && mk) first = base + __ffs(mk) - 1;
        int pos = cnt + __popc(mk & ((1u << lane) - 1u));
        if (valid && pos < KQ) o[pos] = i;
        cnt += __popc(mk);
    }
    if (cnt > KQ) cnt = KQ;
    for (int p = cnt + lane; p < KQ; p += 32) o[p] = first;
}

// ---------------- grouping: SA1 -> grp planes [524288, 32] bf16 hi/lo ----------------
__global__ void k_group1s() {
    int r = blockIdx.x * blockDim.x + threadIdx.x;
    if (r >= BATCH * M1 * KNN1) return;
    int g = r / KNN1;
    int b = g / M1;
    int i = g_ball1[r];
    const float* p = &g_xyz[((size_t)b * NPTS1 + i) * 3];
    const float* c = &g_newxyz1[(size_t)g * 3];
    float d0 = p[0] - c[0], d1 = p[1] - c[1], d2 = p[2] - c[2];
    uint32_t ph0, pl0, ph1, pl1;
    split2pack(d0, d1, ph0, pl0);
    split2pack(d2, 0.f, ph1, pl1);
    uint4 qh = make_uint4(ph0, ph1, 0u, 0u);
    uint4 ql = make_uint4(pl0, pl1, 0u, 0u);
    uint4 z = make_uint4(0u, 0u, 0u, 0u);
    uint4* H = (uint4*)g_grpHi + (size_t)r * 4;
    uint4* L = (uint4*)g_grpLo + (size_t)r * 4;
    H[0] = qh; H[1] = z; H[2] = z; H[3] = z;
    L[0] = ql; L[1] = z; L[2] = z; L[3] = z;
}

// ---------------- grouping: SA2 -> grp planes [262144, 160] bf16 hi/lo ----------------
__global__ void k_group2s() {
    int gw = (blockIdx.x * blockDim.x + threadIdx.x) >> 5;
    int lane = threadIdx.x & 31;
    if (gw >= BATCH * M2 * KNN2) return;
    int g = gw / KNN2;
    int b = g / M2;
    int i = g_ball2[gw];
    uint16_t* oh = &g_grpHi[(size_t)gw * 160];
    uint16_t* ol = &g_grpLo[(size_t)gw * 160];
    const float* c = &g_newxyz2[(size_t)g * 3];
    const float* p = &g_newxyz1[((size_t)b * NPTS2 + i) * 3];
    if (lane < 3) {
        float d = p[lane] - c[lane];
        uint16_t h, l;
        split1(d, h, l);
        oh[lane] = h; ol[lane] = l;
    }
    if (lane >= 3) {  // zero tail cols 131..159
        oh[128 + lane] = 0; ol[128 + lane] = 0;
    }
    const uint16_t* fh = &g_f1Hi[((size_t)b * NPTS2 + i) * 128];
    const uint16_t* fl = &g_f1Lo[((size_t)b * NPTS2 + i) * 128];
#pragma unroll
    for (int c2 = lane; c2 < 128; c2 += 32) {
        oh[3 + c2] = fh[c2];
        ol[3 + c2] = fl[c2];
    }
}

// ============================================================================
// HMMA bf16x3 GEMM, K-chunk 32, double-buffered smem (stride 80, conflict-free),
// ONE __syncthreads per 32-wide chunk. Split-bf16 in; split-bf16 or fp32 out.
// C = relu(A @ W^T + bias); optional max-pool over POOL rows.
// A: hi/lo planes [M, K] (K%32==0, M%128==0). W: hi/lo [N, K].
// ============================================================================
template <int BN, int POOL, int OUTFP32>
__global__ void __launch_bounds__(256) k_mgemm(const uint16_t* __restrict__ Ahi,
                                               const uint16_t* __restrict__ Alo,
                                               const uint16_t* __restrict__ Whi,
                                               const uint16_t* __restrict__ Wlo,
                                               const float* __restrict__ bias,
                                               float* __restrict__ Cf,
                                               uint16_t* __restrict__ Chi,
                                               uint16_t* __restrict__ Clo,
                                               int Mm, int Nn, int Kk) {
    constexpr int WR = (BN == 128) ? 2 : 4;
    constexpr int WC = 8 / WR;
    constexpr int WM = 128 / WR;
    constexpr int WN = BN / WC;
    constexpr int MA = WM / 16;
    constexpr int NA = WN / 8;
    constexpr int ASZ = 128 * 80;          // one bf16 plane, 32 k-cols, 80B stride
    constexpr int BSZ = BN * 80;
    constexpr int STG = 2 * ASZ + 2 * BSZ; // [Ahi][Alo][Bhi][Blo]

    extern __shared__ __align__(16) char sm[];
    uint32_t sb = smem_u32(sm);
    int t = threadIdx.x, lane = t & 31, wid = t >> 5;
    int wrow = wid / WC, wcol = wid % WC;
    int row0 = blockIdx.y * 128, col0 = blockIdx.x * BN;

    int arow = t >> 1, half = t & 1;
    const uint16_t* gAhi = Ahi + (size_t)(row0 + arow) * Kk + half * 8;
    const uint16_t* gAlo = Alo + (size_t)(row0 + arow) * Kk + half * 8;
    bool bact = arow < BN;
    const uint16_t* gWhi = Whi + (size_t)(col0 + arow) * Kk + half * 8;
    const uint16_t* gWlo = Wlo + (size_t)(col0 + arow) * Kk + half * 8;
    uint32_t stoff = (uint32_t)(arow * 80 + half * 16);

    int nch = Kk / 32;

    // prologue: chunk 0 -> stage 0
    {
#pragma unroll
        for (int q = 0; q < 2; q++) {
            *(uint4*)(sm + stoff + q * 32) = *(const uint4*)(gAhi + q * 16);
            *(uint4*)(sm + ASZ + stoff + q * 32) = *(const uint4*)(gAlo + q * 16);
            if (bact) {
                *(uint4*)(sm + 2 * ASZ + stoff + q * 32) = *(const uint4*)(gWhi + q * 16);
                *(uint4*)(sm + 2 * ASZ + BSZ + stoff + q * 32) = *(const uint4*)(gWlo + q * 16);
            }
        }
    }

    int lro = (lane & 7) + ((lane >> 3) & 1) * 8;
    int hob = (lane >> 4) * 16;
    uint32_t bA[MA], bB[2];
#pragma unroll
    for (int ma = 0; ma < MA; ma++)
        bA[ma] = sb + (wrow * WM + ma * 16 + lro) * 80 + hob;
#pragma unroll
    for (int p = 0; p < 2; p++)
        bB[p] = sb + 2 * ASZ + (wcol * WN + p * 16 + lro) * 80 + hob;

    float acc[MA][NA][4];
#pragma unroll
    for (int ma = 0; ma < MA; ma++)
#pragma unroll
        for (int na = 0; na < NA; na++)
#pragma unroll
            for (int q = 0; q < 4; q++) acc[ma][na][q] = 0.f;

    __syncthreads();

    for (int ch = 0; ch < nch; ch++) {
        uint32_t so = (uint32_t)(ch & 1) * STG;
        bool more = (ch + 1) < nch;
        uint4 rA0[2], rA1[2], rB0[2], rB1[2];
        if (more) {
            size_t ko = (size_t)(ch + 1) * 32;
#pragma unroll
            for (int q = 0; q < 2; q++) {
                rA0[q] = *(const uint4*)(gAhi + ko + q * 16);
                rA1[q] = *(const uint4*)(gAlo + ko + q * 16);
            }
            if (bact) {
#pragma unroll
                for (int q = 0; q < 2; q++) {
                    rB0[q] = *(const uint4*)(gWhi + ko + q * 16);
                    rB1[q] = *(const uint4*)(gWlo + ko + q * 16);
                }
            }
        }

#pragma unroll
        for (int kg = 0; kg < 2; kg++) {
            uint32_t kgo = so + kg * 32;
            uint32_t ah[MA][4], al[MA][4], bh[2][4], bl[2][4];
#pragma unroll
            for (int ma = 0; ma < MA; ma++) {
                ldmx4(ah[ma], bA[ma] + kgo);
                ldmx4(al[ma], bA[ma] + kgo + ASZ);
            }
#pragma unroll
            for (int p = 0; p < 2; p++) {
                ldmx4(bh[p], bB[p] + kgo);
                ldmx4(bl[p], bB[p] + kgo + BSZ);
            }
#pragma unroll
            for (int ma = 0; ma < MA; ma++)
#pragma unroll
                for (int na = 0; na < NA; na++) {
                    uint32_t bbh[2] = {bh[na >> 1][na & 1], bh[na >> 1][(na & 1) + 2]};
                    uint32_t bbl[2] = {bl[na >> 1][na & 1], bl[na >> 1][(na & 1) + 2]};
                    mma16816(acc[ma][na], ah[ma], bbh);
                    mma16816(acc[ma][na], ah[ma], bbl);
                    mma16816(acc[ma][na], al[ma], bbh);
                }
        }

        if (more) {
            uint32_t so2 = (uint32_t)((ch + 1) & 1) * STG;
#pragma unroll
            for (int q = 0; q < 2; q++) {
                *(uint4*)(sm + so2 + stoff + q * 32) = rA0[q];
                *(uint4*)(sm + so2 + ASZ + stoff + q * 32) = rA1[q];
            }
            if (bact) {
#pragma unroll
                for (int q = 0; q < 2; q++) {
                    *(uint4*)(sm + so2 + 2 * ASZ + stoff + q * 32) = rB0[q];
                    *(uint4*)(sm + so2 + 2 * ASZ + BSZ + stoff + q * 32) = rB1[q];
                }
            }
        }
        __syncthreads();
    }

    int tg = lane >> 2, t4 = lane & 3;

    if (POOL == 0) {
#pragma unroll
        for (int ma = 0; ma < MA; ma++)
#pragma unroll
            for (int na = 0; na < NA; na++) {
                int cb = col0 + wcol * WN + na * 8 + t4 * 2;
                float b0 = bias[cb], b1 = bias[cb + 1];
#pragma unroll
                for (int h = 0; h < 2; h++) {
                    int r = row0 + wrow * WM + ma * 16 + tg + h * 8;
                    float v0 = fmaxf(acc[ma][na][h * 2 + 0] + b0, 0.f);
                    float v1 = fmaxf(acc[ma][na][h * 2 + 1] + b1, 0.f);
                    uint32_t ph, pl;
                    split2pack(v0, v1, ph, pl);
                    size_t off = (size_t)r * Nn + cb;
                    *(uint32_t*)(Chi + off) = ph;
                    *(uint32_t*)(Clo + off) = pl;
                }
            }
    } else {
        const int NG = 128 / POOL;
        int* red = (int*)(sm + 2 * STG);
        for (int i = t; i < NG * BN; i += 256) red[i] = 0;
        __syncthreads();
#pragma unroll
        for (int ma = 0; ma < MA; ma++)
#pragma unroll
            for (int na = 0; na < NA; na++) {
                int cb = wcol * WN + na * 8 + t4 * 2;
                float b0 = bias[col0 + cb], b1 = bias[col0 + cb + 1];
#pragma unroll
                for (int h = 0; h < 2; h++) {
                    int rt = wrow * WM + ma * 16 + tg + h * 8;
                    int g = rt / POOL;
                    float v0 = fmaxf(acc[ma][na][h * 2 + 0] + b0, 0.f);
                    float v1 = fmaxf(acc[ma][na][h * 2 + 1] + b1, 0.f);
                    atomicMax(&red[g * BN + cb], __float_as_int(v0));
                    atomicMax(&red[g * BN + cb + 1], __float_as_int(v1));
                }
            }
        __syncthreads();
        for (int i = t; i < NG * BN; i += 256) {
            int g = i / BN, lc = i % BN;
            float v = __int_as_float(red[i]);
            size_t off = (size_t)(row0 / POOL + g) * Nn + col0 + lc;
            if (OUTFP32) {
                Cf[off] = v;
            } else {
                uint16_t h, l;
                split1(v, h, l);
                Chi[off] = h;
                Clo[off] = l;
            }
        }
    }
}

// ---------------- warp-per-output GEMV (glob layers, M=32) ----------------
__global__ void k_gemv(const float* __restrict__ A, const float* __restrict__ W,
                       const float* __restrict__ bias, float* __restrict__ C,
                       int M, int N, int K, int relu) {
    int w = (blockIdx.x * blockDim.x + threadIdx.x) >> 5;
    int lane = threadIdx.x & 31;
    if (w >= M * N) return;
    int r = w / N, n = w % N;
    const float* a = A + (size_t)r * K;
    const float* wt = W + (size_t)n * K;
    float s = 0.f;
    for (int k = lane; k < K; k += 32) s = fmaf(a[k], wt[k], s);
#pragma unroll
    for (int o = 16; o > 0; o >>= 1) s += __shfl_down_sync(0xffffffffu, s, o);
    if (lane == 0) {
        s += bias[n];
        if (relu) s = fmaxf(s, 0.f);
        C[w] = s;
    }
}

// ---------------- host ----------------
static void* sym_addr(const void* sym) {
    void* p = nullptr;
    cudaGetSymbolAddress(&p, sym);
    return p;
}

template <int BN, int POOL, int OUTFP32>
static inline void gemm_t(const uint16_t* Ahi, const uint16_t* Alo,
                          const uint16_t* Whi, const uint16_t* Wlo,
                          const float* bias, float* Cf, uint16_t* Chi, uint16_t* Clo,
                          int M, int N, int K) {
    constexpr int SMEM = 2 * (2 * (128 * 80) + 2 * (BN * 80)) + 2048;
    static bool cfg = false;
    if (!cfg) {
        cudaFuncSetAttribute(k_mgemm<BN, POOL, OUTFP32>,
                             cudaFuncAttributeMaxDynamicSharedMemorySize, SMEM);
        cfg = true;
    }
    dim3 grid(N / BN, M / 128);
    k_mgemm<BN, POOL, OUTFP32><<<grid, 256, SMEM>>>(Ahi, Alo, Whi, Wlo, bias, Cf, Chi, Clo, M, N, K);
}

static inline void gemv(const float* A, const float* W, const float* b, float* C,
                        int M, int N, int K, int relu) {
    int warps = M * N;
    k_gemv<<<(warps * 32 + 255) / 256, 256>>>(A, W, b, C, M, N, K, relu);
}

extern "C" void kernel_launch(void* const* d_in, const int* in_sizes, int n_in,
                              void* d_out, int out_size) {
    const float* pts = (const float*)d_in[0];
    const float* sa1w0 = (const float*)d_in[1];  const float* sa1b0 = (const float*)d_in[2];
    const float* sa1w1 = (const float*)d_in[3];  const float* sa1b1 = (const float*)d_in[4];
    const float* sa1w2 = (const float*)d_in[5];  const float* sa1b2 = (const float*)d_in[6];
    const float* sa2w0 = (const float*)d_in[7];  const float* sa2b0 = (const float*)d_in[8];
    const float* sa2w1 = (const float*)d_in[9];  const float* sa2b1 = (const float*)d_in[10];
    const float* sa2w2 = (const float*)d_in[11]; const float* sa2b2 = (const float*)d_in[12];
    const float* locw0 = (const float*)d_in[13]; const float* locb0 = (const float*)d_in[14];
    const float* locw1 = (const float*)d_in[15]; const float* locb1 = (const float*)d_in[16];
    const float* locw2 = (const float*)d_in[17]; const float* locb2 = (const float*)d_in[18];
    const float* glow0 = (const float*)d_in[19]; const float* glob0 = (const float*)d_in[20];
    const float* glow1 = (const float*)d_in[21]; const float* glob1 = (const float*)d_in[22];
    const float* clsw  = (const float*)d_in[23]; const float* clsb  = (const float*)d_in[24];
    float* out = (float*)d_out;

    float* xyz   = (float*)sym_addr(g_xyz);
    float* nx1   = (float*)sym_addr(g_newxyz1);
    float* nx2   = (float*)sym_addr(g_newxyz2);
    int*   ball1 = (int*)  sym_addr(g_ball1);
    int*   ball2 = (int*)  sym_addr(g_ball2);
    uint16_t* whi = (uint16_t*)sym_addr(g_whi);
    uint16_t* wlo = (uint16_t*)sym_addr(g_wlo);
    uint16_t* grpHi = (uint16_t*)sym_addr(g_grpHi);
    uint16_t* grpLo = (uint16_t*)sym_addr(g_grpLo);
    uint16_t* aHi = (uint16_t*)sym_addr(g_aHi);
    uint16_t* aLo = (uint16_t*)sym_addr(g_aLo);
    uint16_t* bHi = (uint16_t*)sym_addr(g_bHi);
    uint16_t* bLo = (uint16_t*)sym_addr(g_bLo);
    uint16_t* f1Hi = (uint16_t*)sym_addr(g_f1Hi);
    uint16_t* f1Lo = (uint16_t*)sym_addr(g_f1Lo);
    uint16_t* f2Hi = (uint16_t*)sym_addr(g_f2Hi);
    uint16_t* f2Lo = (uint16_t*)sym_addr(g_f2Lo);
    float* pool = (float*)sym_addr(g_pool);
    float* gg1  = (float*)sym_addr(g_g1);
    float* gg2  = (float*)sym_addr(g_g2);

    const float R2_1 = (float)(0.2 * 0.2);
    const float R2_2 = (float)(0.4 * 0.4);

    // 0. batched weight split (one launch), K padded to x32
    {
        WSplitArgs a;
        const float* srcs[9] = {sa1w0, sa1w1, sa1w2, sa2w0, sa2w1, sa2w2, locw0, locw1, locw2};
        int offs[9]  = {OW0, OW1, OW2, OS0, OS1, OS2, OL0, OL1, OL2};
        int Ns[9]    = {64, 64, 128, 128, 128, 256, 256, 512, 1024};
        int Kins[9]  = {3, 64, 64, 131, 128, 128, 256, 256, 512};
        int Kpads[9] = {32, 64, 64, 160, 128, 128, 256, 256, 512};
        for (int j = 0; j < 9; j++) {
            a.src[j] = srcs[j]; a.off[j] = offs[j]; a.N[j] = Ns[j];
            a.Kin[j] = Kins[j]; a.Kpad[j] = Kpads[j];
        }
        k_wsplit_all<<<(WTOTAL + 255) / 256, 256>>>(a, whi, wlo);
    }

    // 1. transpose
    k_transpose<<<(BATCH * 3 * NPTS1 + 255) / 256, 256>>>(pts);

    // 2. SA1
    k_fps<8, NPTS1, M1><<<BATCH, 1024>>>(xyz, nx1);
    k_ballquery<NPTS1, M1, KNN1><<<(BATCH * M1) / 8, 256>>>(xyz, nx1, R2_1, ball1);
    k_group1s<<<(BATCH * M1 * KNN1 + 255) / 256, 256>>>();
    gemm_t<64, 0, 0>(grpHi, grpLo, whi + OW0, wlo + OW0, sa1b0, nullptr, aHi, aLo,
                     BATCH * M1 * KNN1, 64, 32);
    gemm_t<64, 0, 0>(aHi, aLo, whi + OW1, wlo + OW1, sa1b1, nullptr, bHi, bLo,
                     BATCH * M1 * KNN1, 64, 64);
    gemm_t<128, KNN1, 0>(bHi, bLo, whi + OW2, wlo + OW2, sa1b2, nullptr, f1Hi, f1Lo,
                         BATCH * M1 * KNN1, 128, 64);

    // 3. SA2
    k_fps<1, NPTS2, M2><<<BATCH, 512>>>(nx1, nx2);
    k_ballquery<NPTS2, M2, KNN2><<<(BATCH * M2) / 8, 256>>>(nx1, nx2, R2_2, ball2);
    k_group2s<<<(BATCH * M2 * KNN2 * 32 + 255) / 256, 256>>>();
    gemm_t<128, 0, 0>(grpHi, grpLo, whi + OS0, wlo + OS0, sa2b0, nullptr, aHi, aLo,
                      BATCH * M2 * KNN2, 128, 160);
    gemm_t<128, 0, 0>(aHi, aLo, whi + OS1, wlo + OS1, sa2b1, nullptr, bHi, bLo,
                      BATCH * M2 * KNN2, 128, 128);
    gemm_t<128, KNN2, 0>(bHi, bLo, whi + OS2, wlo + OS2, sa2b2, nullptr, f2Hi, f2Lo,
                         BATCH * M2 * KNN2, 256, 128);

    // 4. loc MLP + global max-pool (BN=64 on small-grid layers for more CTAs)
    gemm_t<64, 0, 0>(f2Hi, f2Lo, whi + OL0, wlo + OL0, locb0, nullptr, aHi, aLo,
                     BATCH * M2, 256, 256);
    gemm_t<64, 0, 0>(aHi, aLo, whi + OL1, wlo + OL1, locb1, nullptr, bHi, bLo,
                     BATCH * M2, 512, 256);
    gemm_t<128, 128, 1>(bHi, bLo, whi + OL2, wlo + OL2, locb2, pool, nullptr, nullptr,
                        BATCH * M2, 1024, 512);

    // 5. global MLP: warp-per-output GEMV
    gemv(pool, glow0, glob0, gg1, BATCH, 512, 1024, 1);
    gemv(gg1,  glow1, glob1, gg2, BATCH, 256, 512, 1);
    gemv(gg2,  clsw,  clsb,  out, BATCH, 40, 256, 0);
}

// round 17
// speedup vs baseline: 1.7197x; 1.0496x over previous
#include <cuda_runtime.h>
#include <cuda_bf16.h>
#include <cstdint>
#include <cstddef>

#define BATCH 32
#define NPTS1 8192
#define M1 512
#define KNN1 32
#define M2 128
#define KNN2 64
#define NPTS2 512

// ---------------- scratch (static device globals) ----------------
__device__ __align__(16) float g_xyz[BATCH * NPTS1 * 3];
__device__ __align__(16) float g_newxyz1[BATCH * M1 * 3];
__device__ __align__(16) float g_newxyz2[BATCH * M2 * 3];
__device__ int   g_ball1[BATCH * M1 * KNN1];
__device__ int   g_ball2[BATCH * M2 * KNN2];

// split bf16 planes
__device__ uint16_t g_whi[804864];
__device__ uint16_t g_wlo[804864];
__device__ uint16_t g_grpHi[262144 * 160];
__device__ uint16_t g_grpLo[262144 * 160];
__device__ uint16_t g_aHi[524288 * 64];
__device__ uint16_t g_aLo[524288 * 64];
__device__ uint16_t g_bHi[524288 * 64];
__device__ uint16_t g_bLo[524288 * 64];
__device__ uint16_t g_f1Hi[16384 * 128];
__device__ uint16_t g_f1Lo[16384 * 128];
__device__ uint16_t g_f2Hi[4096 * 256];
__device__ uint16_t g_f2Lo[4096 * 256];

__device__ float g_pool[BATCH * 1024];
__device__ float g_g1[BATCH * 512];
__device__ float g_g2[BATCH * 256];

// weight plane offsets (elements), K padded to multiple of 32
#define OW0 0        // 64 x 32 (unused by GEMM now; kept for layout stability)
#define OW1 2048     // 64 x 64
#define OW2 6144     // 128 x 64
#define OS0 14336    // 128 x 160
#define OS1 34816    // 128 x 128
#define OS2 51200    // 256 x 128
#define OL0 83968    // 256 x 256
#define OL1 149504   // 512 x 256
#define OL2 280576   // 1024 x 512
#define WTOTAL 804864

// ---------------- helpers ----------------
__device__ __forceinline__ uint32_t smem_u32(const void* p) {
    uint32_t a;
    asm("{ .reg .u64 t; cvta.to.shared.u64 t, %1; cvt.u32.u64 %0, t; }" : "=r"(a) : "l"(p));
    return a;
}
__device__ __forceinline__ void ldmx4(uint32_t* r, uint32_t a) {
    asm volatile("ldmatrix.sync.aligned.m8n8.x4.shared.b16 {%0,%1,%2,%3}, [%4];"
                 : "=r"(r[0]), "=r"(r[1]), "=r"(r[2]), "=r"(r[3]) : "r"(a));
}
__device__ __forceinline__ void mma16816(float* c, const uint32_t* a, const uint32_t* b) {
    asm volatile("mma.sync.aligned.m16n8k16.row.col.f32.bf16.bf16.f32 "
                 "{%0,%1,%2,%3}, {%4,%5,%6,%7}, {%8,%9}, {%0,%1,%2,%3};"
                 : "+f"(c[0]), "+f"(c[1]), "+f"(c[2]), "+f"(c[3])
                 : "r"(a[0]), "r"(a[1]), "r"(a[2]), "r"(a[3]), "r"(b[0]), "r"(b[1]));
}
__device__ __forceinline__ uint32_t pack_bf(__nv_bfloat16 a, __nv_bfloat16 b) {
    return ((uint32_t)__bfloat16_as_ushort(b) << 16) | __bfloat16_as_ushort(a);
}
__device__ __forceinline__ void split1(float v, uint16_t& h, uint16_t& l) {
    __nv_bfloat16 hb = __float2bfloat16(v);
    h = __bfloat16_as_ushort(hb);
    l = __bfloat16_as_ushort(__float2bfloat16(v - __bfloat162float(hb)));
}
__device__ __forceinline__ void split2pack(float v0, float v1, uint32_t& ph, uint32_t& pl) {
    __nv_bfloat16 h0 = __float2bfloat16(v0), h1 = __float2bfloat16(v1);
    __nv_bfloat16 l0 = __float2bfloat16(v0 - __bfloat162float(h0));
    __nv_bfloat16 l1 = __float2bfloat16(v1 - __bfloat162float(h1));
    ph = pack_bf(h0, h1);
    pl = pack_bf(l0, l1);
}

// ---------------- transpose ----------------
__global__ void k_transpose(const float* __restrict__ pts) {
    int idx = blockIdx.x * blockDim.x + threadIdx.x;
    if (idx >= BATCH * 3 * NPTS1) return;
    int b = idx / (3 * NPTS1);
    int r = idx % (3 * NPTS1);
    int c = r / NPTS1;
    int n = r % NPTS1;
    g_xyz[(b * NPTS1 + n) * 3 + c] = pts[idx];
}

// ---------------- batched weight split ----------------
struct WSplitArgs {
    const float* src[9];
    int off[9];
    int N[9];
    int Kin[9];
    int Kpad[9];
};

__global__ void k_wsplit_all(WSplitArgs a, uint16_t* __restrict__ hi, uint16_t* __restrict__ lo) {
    int i = blockIdx.x * blockDim.x + threadIdx.x;
    if (i >= WTOTAL) return;
    int s = 0;
#pragma unroll
    for (int j = 1; j < 9; j++)
        if (i >= a.off[j]) s = j;
    int local = i - a.off[s];
    int kp = a.Kpad[s];
    int r = local / kp, k = local % kp;
    float v = (k < a.Kin[s]) ? a.src[s][r * a.Kin[s] + k] : 0.f;
    split1(v, hi[i], lo[i]);
}

// ---------------- farthest point sampling ----------------
template <int P, int NP, int MSEL>
__global__ void k_fps(const float* __restrict__ xyz, float* __restrict__ new_xyz) {
    int b = blockIdx.x, tid = threadIdx.x, T = blockDim.x;
    float px[P], py[P], pz[P], pd[P];
#pragma unroll
    for (int j = 0; j < P; j++) {
        int i = j * T + tid;
        const float* p = &xyz[(b * NP + i) * 3];
        px[j] = p[0]; py[j] = p[1]; pz[j] = p[2];
        pd[j] = 1e10f;
    }
    __shared__ float s_cx, s_cy, s_cz;
    __shared__ float s_val[32];
    __shared__ int   s_idx[32];
    if (tid == 0) {
        const float* p = &xyz[(size_t)b * NP * 3];
        s_cx = p[0]; s_cy = p[1]; s_cz = p[2];
        float* o = &new_xyz[(size_t)b * MSEL * 3];
        o[0] = p[0]; o[1] = p[1]; o[2] = p[2];
    }
    __syncthreads();
    int nw = T >> 5;
    for (int it = 1; it < MSEL; it++) {
        float cx = s_cx, cy = s_cy, cz = s_cz;
        float bv = -1.0f; int bi = NP;
#pragma unroll
        for (int j = 0; j < P; j++) {
            int i = j * T + tid;
            float dx = px[j] - cx, dy = py[j] - cy, dz = pz[j] - cz;
            float d = fmaf(dz, dz, fmaf(dy, dy, dx * dx));
            d = fminf(pd[j], d);
            pd[j] = d;
            if (d > bv || (d == bv && i < bi)) { bv = d; bi = i; }
        }
#pragma unroll
        for (int off = 16; off > 0; off >>= 1) {
            float ov = __shfl_down_sync(0xffffffffu, bv, off);
            int   oi = __shfl_down_sync(0xffffffffu, bi, off);
            if (ov > bv || (ov == bv && oi < bi)) { bv = ov; bi = oi; }
        }
        int w = tid >> 5;
        if ((tid & 31) == 0) { s_val[w] = bv; s_idx[w] = bi; }
        __syncthreads();
        if (w == 0) {
            int lane = tid & 31;
            bv = (lane < nw) ? s_val[lane] : -2.0f;
            bi = (lane < nw) ? s_idx[lane] : NP;
#pragma unroll
            for (int off = 16; off > 0; off >>= 1) {
                float ov = __shfl_down_sync(0xffffffffu, bv, off);
                int   oi = __shfl_down_sync(0xffffffffu, bi, off);
                if (ov > bv || (ov == bv && oi < bi)) { bv = ov; bi = oi; }
            }
            if (lane == 0) {
                const float* p = &xyz[((size_t)b * NP + bi) * 3];
                s_cx = p[0]; s_cy = p[1]; s_cz = p[2];
                float* o = &new_xyz[((size_t)b * MSEL + it) * 3];
                o[0] = p[0]; o[1] = p[1]; o[2] = p[2];
            }
        }
        __syncthreads();
    }
}

// ---------------- ball query: 4 points/lane, empty-iteration fast path ----------------
template <int NP, int MSEL, int KQ>
__global__ void k_ballquery4(const float* __restrict__ xyz, const float* __restrict__ cent,
                             float R2, int* __restrict__ out) {
    const unsigned FULL = 0xffffffffu;
    int gw = (blockIdx.x * blockDim.x + threadIdx.x) >> 5;
    int lane = threadIdx.x & 31;
    if (gw >= BATCH * MSEL) return;
    int b = gw / MSEL, m = gw % MSEL;
    const float* cp = &cent[((size_t)b * MSEL + m) * 3];
    float cx = cp[0], cy = cp[1], cz = cp[2];
    const float4* xb4 = (const float4*)(xyz + (size_t)b * NP * 3);
    int* o = &out[((size_t)b * MSEL + m) * KQ];
    int cnt = 0, first = -1;

    for (int base = 0; base < NP; base += 128) {
        const float4* q = xb4 + (base * 3) / 4 + lane * 3;
        float4 q0 = q[0], q1 = q[1], q2 = q[2];
        float dx, dy, dz;
        dx = q0.x - cx; dy = q0.y - cy; dz = q0.z - cz;
        float e0 = fmaf(dz, dz, fmaf(dy, dy, dx * dx));
        dx = q0.w - cx; dy = q1.x - cy; dz = q1.y - cz;
        float e1 = fmaf(dz, dz, fmaf(dy, dy, dx * dx));
        dx = q1.z - cx; dy = q1.w - cy; dz = q2.x - cz;
        float e2 = fmaf(dz, dz, fmaf(dy, dy, dx * dx));
        dx = q2.y - cx; dy = q2.z - cy; dz = q2.w - cz;
        float e3 = fmaf(dz, dz, fmaf(dy, dy, dx * dx));
        unsigned nib = (unsigned)(e0 < R2) | ((unsigned)(e1 < R2) << 1) |
                       ((unsigned)(e2 < R2) << 2) | ((unsigned)(e3 < R2) << 3);
        unsigned any = __ballot_sync(FULL, nib != 0u);
        if (!any) continue;

        if (first < 0) {
            int fl = __ffs(any) - 1;
            unsigned nf = __shfl_sync(FULL, nib, fl);
            first = base + 4 * fl + __ffs(nf) - 1;
        }
        int c = __popc(nib);
        int incl = c;
#pragma unroll
        for (int off = 1; off < 32; off <<= 1) {
            int u = __shfl_up_sync(FULL, incl, off);
            if (lane >= off) incl += u;
        }
        int total = __shfl_sync(FULL, incl, 31);
        int p = cnt + incl - c;
#pragma unroll
        for (int j = 0; j < 4; j++) {
            if ((nib >> j) & 1u) {
                if (p < KQ) o[p] = base + 4 * lane + j;
                p++;
            }
        }
        cnt += total;
        if (cnt >= KQ) break;   // all KQ slots written; outputs final
    }
    if (cnt > KQ) cnt = KQ;
    for (int p = cnt + lane; p < KQ; p += 32) o[p] = first;
}

// ---------------- fused group1 + SA1-L0 (K=3 matvec, exact fp32) ----------------
// One warp per grouped row: out[r][n] = relu(w0[n]·relxyz + b0[n]), n = 2*lane{,+1}.
__global__ void k_sa1l0(const float* __restrict__ w, const float* __restrict__ bias) {
    int gw = (blockIdx.x * blockDim.x + threadIdx.x) >> 5;
    int lane = threadIdx.x & 31;
    if (gw >= BATCH * M1 * KNN1) return;
    int g = gw / KNN1;
    int b = g / M1;
    int i = g_ball1[gw];
    const float* p = &g_xyz[((size_t)b * NPTS1 + i) * 3];
    const float* c = &g_newxyz1[(size_t)g * 3];
    float d0 = p[0] - c[0], d1 = p[1] - c[1], d2 = p[2] - c[2];
    int n = lane * 2;
    const float* w0 = w + n * 3;
    float v0 = fmaf(w0[2], d2, fmaf(w0[1], d1, w0[0] * d0)) + bias[n];
    float v1 = fmaf(w0[5], d2, fmaf(w0[4], d1, w0[3] * d0)) + bias[n + 1];
    v0 = fmaxf(v0, 0.f);
    v1 = fmaxf(v1, 0.f);
    uint32_t ph, pl;
    split2pack(v0, v1, ph, pl);
    ((uint32_t*)g_aHi)[(size_t)gw * 32 + lane] = ph;
    ((uint32_t*)g_aLo)[(size_t)gw * 32 + lane] = pl;
}

// ---------------- grouping: SA2 -> grp planes [262144, 160] bf16 hi/lo ----------------
__global__ void k_group2s() {
    int gw = (blockIdx.x * blockDim.x + threadIdx.x) >> 5;
    int lane = threadIdx.x & 31;
    if (gw >= BATCH * M2 * KNN2) return;
    int g = gw / KNN2;
    int b = g / M2;
    int i = g_ball2[gw];
    uint16_t* oh = &g_grpHi[(size_t)gw * 160];
    uint16_t* ol = &g_grpLo[(size_t)gw * 160];
    const float* c = &g_newxyz2[(size_t)g * 3];
    const float* p = &g_newxyz1[((size_t)b * NPTS2 + i) * 3];
    if (lane < 3) {
        float d = p[lane] - c[lane];
        uint16_t h, l;
        split1(d, h, l);
        oh[lane] = h; ol[lane] = l;
    }
    if (lane >= 3) {  // zero tail cols 131..159
        oh[128 + lane] = 0; ol[128 + lane] = 0;
    }
    const uint16_t* fh = &g_f1Hi[((size_t)b * NPTS2 + i) * 128];
    const uint16_t* fl = &g_f1Lo[((size_t)b * NPTS2 + i) * 128];
#pragma unroll
    for (int c2 = lane; c2 < 128; c2 += 32) {
        oh[3 + c2] = fh[c2];
        ol[3 + c2] = fl[c2];
    }
}

// ============================================================================
// HMMA bf16x3 GEMM, K-chunk 32, double-buffered smem (stride 80, conflict-free),
// ONE __syncthreads per 32-wide chunk. Split-bf16 in; split-bf16 or fp32 out.
// ============================================================================
template <int BN, int POOL, int OUTFP32>
__global__ void __launch_bounds__(256) k_mgemm(const uint16_t* __restrict__ Ahi,
                                               const uint16_t* __restrict__ Alo,
                                               const uint16_t* __restrict__ Whi,
                                               const uint16_t* __restrict__ Wlo,
                                               const float* __restrict__ bias,
                                               float* __restrict__ Cf,
                                               uint16_t* __restrict__ Chi,
                                               uint16_t* __restrict__ Clo,
                                               int Mm, int Nn, int Kk) {
    constexpr int WR = (BN == 128) ? 2 : 4;
    constexpr int WC = 8 / WR;
    constexpr int WM = 128 / WR;
    constexpr int WN = BN / WC;
    constexpr int MA = WM / 16;
    constexpr int NA = WN / 8;
    constexpr int ASZ = 128 * 80;
    constexpr int BSZ = BN * 80;
    constexpr int STG = 2 * ASZ + 2 * BSZ;

    extern __shared__ __align__(16) char sm[];
    uint32_t sb = smem_u32(sm);
    int t = threadIdx.x, lane = t & 31, wid = t >> 5;
    int wrow = wid / WC, wcol = wid % WC;
    int row0 = blockIdx.y * 128, col0 = blockIdx.x * BN;

    int arow = t >> 1, half = t & 1;
    const uint16_t* gAhi = Ahi + (size_t)(row0 + arow) * Kk + half * 8;
    const uint16_t* gAlo = Alo + (size_t)(row0 + arow) * Kk + half * 8;
    bool bact = arow < BN;
    const uint16_t* gWhi = Whi + (size_t)(col0 + arow) * Kk + half * 8;
    const uint16_t* gWlo = Wlo + (size_t)(col0 + arow) * Kk + half * 8;
    uint32_t stoff = (uint32_t)(arow * 80 + half * 16);

    int nch = Kk / 32;

    {
#pragma unroll
        for (int q = 0; q < 2; q++) {
            *(uint4*)(sm + stoff + q * 32) = *(const uint4*)(gAhi + q * 16);
            *(uint4*)(sm + ASZ + stoff + q * 32) = *(const uint4*)(gAlo + q * 16);
            if (bact) {
                *(uint4*)(sm + 2 * ASZ + stoff + q * 32) = *(const uint4*)(gWhi + q * 16);
                *(uint4*)(sm + 2 * ASZ + BSZ + stoff + q * 32) = *(const uint4*)(gWlo + q * 16);
            }
        }
    }

    int lro = (lane & 7) + ((lane >> 3) & 1) * 8;
    int hob = (lane >> 4) * 16;
    uint32_t bA[MA], bB[2];
#pragma unroll
    for (int ma = 0; ma < MA; ma++)
        bA[ma] = sb + (wrow * WM + ma * 16 + lro) * 80 + hob;
#pragma unroll
    for (int p = 0; p < 2; p++)
        bB[p] = sb + 2 * ASZ + (wcol * WN + p * 16 + lro) * 80 + hob;

    float acc[MA][NA][4];
#pragma unroll
    for (int ma = 0; ma < MA; ma++)
#pragma unroll
        for (int na = 0; na < NA; na++)
#pragma unroll
            for (int q = 0; q < 4; q++) acc[ma][na][q] = 0.f;

    __syncthreads();

    for (int ch = 0; ch < nch; ch++) {
        uint32_t so = (uint32_t)(ch & 1) * STG;
        bool more = (ch + 1) < nch;
        uint4 rA0[2], rA1[2], rB0[2], rB1[2];
        if (more) {
            size_t ko = (size_t)(ch + 1) * 32;
#pragma unroll
            for (int q = 0; q < 2; q++) {
                rA0[q] = *(const uint4*)(gAhi + ko + q * 16);
                rA1[q] = *(const uint4*)(gAlo + ko + q * 16);
            }
            if (bact) {
#pragma unroll
                for (int q = 0; q < 2; q++) {
                    rB0[q] = *(const uint4*)(gWhi + ko + q * 16);
                    rB1[q] = *(const uint4*)(gWlo + ko + q * 16);
                }
            }
        }

#pragma unroll
        for (int kg = 0; kg < 2; kg++) {
            uint32_t kgo = so + kg * 32;
            uint32_t ah[MA][4], al[MA][4], bh[2][4], bl[2][4];
#pragma unroll
            for (int ma = 0; ma < MA; ma++) {
                ldmx4(ah[ma], bA[ma] + kgo);
                ldmx4(al[ma], bA[ma] + kgo + ASZ);
            }
#pragma unroll
            for (int p = 0; p < 2; p++) {
                ldmx4(bh[p], bB[p] + kgo);
                ldmx4(bl[p], bB[p] + kgo + BSZ);
            }
#pragma unroll
            for (int ma = 0; ma < MA; ma++)
#pragma unroll
                for (int na = 0; na < NA; na++) {
                    uint32_t bbh[2] = {bh[na >> 1][na & 1], bh[na >> 1][(na & 1) + 2]};
                    uint32_t bbl[2] = {bl[na >> 1][na & 1], bl[na >> 1][(na & 1) + 2]};
                    mma16816(acc[ma][na], ah[ma], bbh);
                    mma16816(acc[ma][na], ah[ma], bbl);
                    mma16816(acc[ma][na], al[ma], bbh);
                }
        }

        if (more) {
            uint32_t so2 = (uint32_t)((ch + 1) & 1) * STG;
#pragma unroll
            for (int q = 0; q < 2; q++) {
                *(uint4*)(sm + so2 + stoff + q * 32) = rA0[q];
                *(uint4*)(sm + so2 + ASZ + stoff + q * 32) = rA1[q];
            }
            if (bact) {
#pragma unroll
                for (int q = 0; q < 2; q++) {
                    *(uint4*)(sm + so2 + 2 * ASZ + stoff + q * 32) = rB0[q];
                    *(uint4*)(sm + so2 + 2 * ASZ + BSZ + stoff + q * 32) = rB1[q];
                }
            }
        }
        __syncthreads();
    }

    int tg = lane >> 2, t4 = lane & 3;

    if (POOL == 0) {
#pragma unroll
        for (int ma = 0; ma < MA; ma++)
#pragma unroll
            for (int na = 0; na < NA; na++) {
                int cb = col0 + wcol * WN + na * 8 + t4 * 2;
                float b0 = bias[cb], b1 = bias[cb + 1];
#pragma unroll
                for (int h = 0; h < 2; h++) {
                    int r = row0 + wrow * WM + ma * 16 + tg + h * 8;
                    float v0 = fmaxf(acc[ma][na][h * 2 + 0] + b0, 0.f);
                    float v1 = fmaxf(acc[ma][na][h * 2 + 1] + b1, 0.f);
                    uint32_t ph, pl;
                    split2pack(v0, v1, ph, pl);
                    size_t off = (size_t)r * Nn + cb;
                    *(uint32_t*)(Chi + off) = ph;
                    *(uint32_t*)(Clo + off) = pl;
                }
            }
    } else {
        const int NG = 128 / POOL;
        int* red = (int*)(sm + 2 * STG);
        for (int i = t; i < NG * BN; i += 256) red[i] = 0;
        __syncthreads();
#pragma unroll
        for (int ma = 0; ma < MA; ma++)
#pragma unroll
            for (int na = 0; na < NA; na++) {
                int cb = wcol * WN + na * 8 + t4 * 2;
                float b0 = bias[col0 + cb], b1 = bias[col0 + cb + 1];
#pragma unroll
                for (int h = 0; h < 2; h++) {
                    int rt = wrow * WM + ma * 16 + tg + h * 8;
                    int g = rt / POOL;
                    float v0 = fmaxf(acc[ma][na][h * 2 + 0] + b0, 0.f);
                    float v1 = fmaxf(acc[ma][na][h * 2 + 1] + b1, 0.f);
                    atomicMax(&red[g * BN + cb], __float_as_int(v0));
                    atomicMax(&red[g * BN + cb + 1], __float_as_int(v1));
                }
            }
        __syncthreads();
        for (int i = t; i < NG * BN; i += 256) {
            int g = i / BN, lc = i % BN;
            float v = __int_as_float(red[i]);
            size_t off = (size_t)(row0 / POOL + g) * Nn + col0 + lc;
            if (OUTFP32) {
                Cf[off] = v;
            } else {
                uint16_t h, l;
                split1(v, h, l);
                Chi[off] = h;
                Clo[off] = l;
            }
        }
    }
}

// ---------------- warp-per-output GEMV (glob layers, M=32) ----------------
__global__ void k_gemv(const float* __restrict__ A, const float* __restrict__ W,
                       const float* __restrict__ bias, float* __restrict__ C,
                       int M, int N, int K, int relu) {
    int w = (blockIdx.x * blockDim.x + threadIdx.x) >> 5;
    int lane = threadIdx.x & 31;
    if (w >= M * N) return;
    int r = w / N, n = w % N;
    const float* a = A + (size_t)r * K;
    const float* wt = W + (size_t)n * K;
    float s = 0.f;
    for (int k = lane; k < K; k += 32) s = fmaf(a[k], wt[k], s);
#pragma unroll
    for (int o = 16; o > 0; o >>= 1) s += __shfl_down_sync(0xffffffffu, s, o);
    if (lane == 0) {
        s += bias[n];
        if (relu) s = fmaxf(s, 0.f);
        C[w] = s;
    }
}

// ---------------- host ----------------
static void* sym_addr(const void* sym) {
    void* p = nullptr;
    cudaGetSymbolAddress(&p, sym);
    return p;
}

template <int BN, int POOL, int OUTFP32>
static inline void gemm_t(const uint16_t* Ahi, const uint16_t* Alo,
                          const uint16_t* Whi, const uint16_t* Wlo,
                          const float* bias, float* Cf, uint16_t* Chi, uint16_t* Clo,
                          int M, int N, int K) {
    constexpr int SMEM = 2 * (2 * (128 * 80) + 2 * (BN * 80)) + 2048;
    static bool cfg = false;
    if (!cfg) {
        cudaFuncSetAttribute(k_mgemm<BN, POOL, OUTFP32>,
                             cudaFuncAttributeMaxDynamicSharedMemorySize, SMEM);
        cfg = true;
    }
    dim3 grid(N / BN, M / 128);
    k_mgemm<BN, POOL, OUTFP32><<<grid, 256, SMEM>>>(Ahi, Alo, Whi, Wlo, bias, Cf, Chi, Clo, M, N, K);
}

static inline void gemv(const float* A, const float* W, const float* b, float* C,
                        int M, int N, int K, int relu) {
    int warps = M * N;
    k_gemv<<<(warps * 32 + 255) / 256, 256>>>(A, W, b, C, M, N, K, relu);
}

extern "C" void kernel_launch(void* const* d_in, const int* in_sizes, int n_in,
                              void* d_out, int out_size) {
    const float* pts = (const float*)d_in[0];
    const float* sa1w0 = (const float*)d_in[1];  const float* sa1b0 = (const float*)d_in[2];
    const float* sa1w1 = (const float*)d_in[3];  const float* sa1b1 = (const float*)d_in[4];
    const float* sa1w2 = (const float*)d_in[5];  const float* sa1b2 = (const float*)d_in[6];
    const float* sa2w0 = (const float*)d_in[7];  const float* sa2b0 = (const float*)d_in[8];
    const float* sa2w1 = (const float*)d_in[9];  const float* sa2b1 = (const float*)d_in[10];
    const float* sa2w2 = (const float*)d_in[11]; const float* sa2b2 = (const float*)d_in[12];
    const float* locw0 = (const float*)d_in[13]; const float* locb0 = (const float*)d_in[14];
    const float* locw1 = (const float*)d_in[15]; const float* locb1 = (const float*)d_in[16];
    const float* locw2 = (const float*)d_in[17]; const float* locb2 = (const float*)d_in[18];
    const float* glow0 = (const float*)d_in[19]; const float* glob0 = (const float*)d_in[20];
    const float* glow1 = (const float*)d_in[21]; const float* glob1 = (const float*)d_in[22];
    const float* clsw  = (const float*)d_in[23]; const float* clsb  = (const float*)d_in[24];
    float* out = (float*)d_out;

    float* xyz   = (float*)sym_addr(g_xyz);
    float* nx1   = (float*)sym_addr(g_newxyz1);
    float* nx2   = (float*)sym_addr(g_newxyz2);
    int*   ball1 = (int*)  sym_addr(g_ball1);
    int*   ball2 = (int*)  sym_addr(g_ball2);
    uint16_t* whi = (uint16_t*)sym_addr(g_whi);
    uint16_t* wlo = (uint16_t*)sym_addr(g_wlo);
    uint16_t* grpHi = (uint16_t*)sym_addr(g_grpHi);
    uint16_t* grpLo = (uint16_t*)sym_addr(g_grpLo);
    uint16_t* aHi = (uint16_t*)sym_addr(g_aHi);
    uint16_t* aLo = (uint16_t*)sym_addr(g_aLo);
    uint16_t* bHi = (uint16_t*)sym_addr(g_bHi);
    uint16_t* bLo = (uint16_t*)sym_addr(g_bLo);
    uint16_t* f1Hi = (uint16_t*)sym_addr(g_f1Hi);
    uint16_t* f1Lo = (uint16_t*)sym_addr(g_f1Lo);
    uint16_t* f2Hi = (uint16_t*)sym_addr(g_f2Hi);
    uint16_t* f2Lo = (uint16_t*)sym_addr(g_f2Lo);
    float* pool = (float*)sym_addr(g_pool);
    float* gg1  = (float*)sym_addr(g_g1);
    float* gg2  = (float*)sym_addr(g_g2);

    const float R2_1 = (float)(0.2 * 0.2);
    const float R2_2 = (float)(0.4 * 0.4);

    // 0. batched weight split (one launch), K padded to x32
    {
        WSplitArgs a;
        const float* srcs[9] = {sa1w0, sa1w1, sa1w2, sa2w0, sa2w1, sa2w2, locw0, locw1, locw2};
        int offs[9]  = {OW0, OW1, OW2, OS0, OS1, OS2, OL0, OL1, OL2};
        int Ns[9]    = {64, 64, 128, 128, 128, 256, 256, 512, 1024};
        int Kins[9]  = {3, 64, 64, 131, 128, 128, 256, 256, 512};
        int Kpads[9] = {32, 64, 64, 160, 128, 128, 256, 256, 512};
        for (int j = 0; j < 9; j++) {
            a.src[j] = srcs[j]; a.off[j] = offs[j]; a.N[j] = Ns[j];
            a.Kin[j] = Kins[j]; a.Kpad[j] = Kpads[j];
        }
        k_wsplit_all<<<(WTOTAL + 255) / 256, 256>>>(a, whi, wlo);
    }

    // 1. transpose
    k_transpose<<<(BATCH * 3 * NPTS1 + 255) / 256, 256>>>(pts);

    // 2. SA1
    k_fps<8, NPTS1, M1><<<BATCH, 1024>>>(xyz, nx1);
    k_ballquery4<NPTS1, M1, KNN1><<<(BATCH * M1) / 8, 256>>>(xyz, nx1, R2_1, ball1);
    k_sa1l0<<<(BATCH * M1 * KNN1 * 32 + 255) / 256, 256>>>(sa1w0, sa1b0);   // fused group+L0
    gemm_t<64, 0, 0>(aHi, aLo, whi + OW1, wlo + OW1, sa1b1, nullptr, bHi, bLo,
                     BATCH * M1 * KNN1, 64, 64);
    gemm_t<128, KNN1, 0>(bHi, bLo, whi + OW2, wlo + OW2, sa1b2, nullptr, f1Hi, f1Lo,
                         BATCH * M1 * KNN1, 128, 64);

    // 3. SA2
    k_fps<1, NPTS2, M2><<<BATCH, 512>>>(nx1, nx2);
    k_ballquery4<NPTS2, M2, KNN2><<<(BATCH * M2) / 8, 256>>>(nx1, nx2, R2_2, ball2);
    k_group2s<<<(BATCH * M2 * KNN2 * 32 + 255) / 256, 256>>>();
    gemm_t<128, 0, 0>(grpHi, grpLo, whi + OS0, wlo + OS0, sa2b0, nullptr, aHi, aLo,
                      BATCH * M2 * KNN2, 128, 160);
    gemm_t<128, 0, 0>(aHi, aLo, whi + OS1, wlo + OS1, sa2b1, nullptr, bHi, bLo,
                      BATCH * M2 * KNN2, 128, 128);
    gemm_t<128, KNN2, 0>(bHi, bLo, whi + OS2, wlo + OS2, sa2b2, nullptr, f2Hi, f2Lo,
                         BATCH * M2 * KNN2, 256, 128);

    // 4. loc MLP + global max-pool
    gemm_t<64, 0, 0>(f2Hi, f2Lo, whi + OL0, wlo + OL0, locb0, nullptr, aHi, aLo,
                     BATCH * M2, 256, 256);
    gemm_t<64, 0, 0>(aHi, aLo, whi + OL1, wlo + OL1, locb1, nullptr, bHi, bLo,
                     BATCH * M2, 512, 256);
    gemm_t<128, 128, 1>(bHi, bLo, whi + OL2, wlo + OL2, locb2, pool, nullptr, nullptr,
                        BATCH * M2, 1024, 512);

    // 5. global MLP: warp-per-output GEMV
    gemv(pool, glow0, glob0, gg1, BATCH, 512, 1024, 1);
    gemv(gg1,  glow1, glob1, gg2, BATCH, 256, 512, 1);
    gemv(gg2,  clsw,  clsb,  out, BATCH, 40, 256, 0);
}